// round 15
// baseline (speedup 1.0000x reference)
#include <cuda_runtime.h>
#include <math.h>

#define MM 1024
#define NPT 128
#define AA 225
#define NSK 8

typedef unsigned long long ull;

__device__ __forceinline__ ull fma2(ull a, ull b, ull c) {
    ull d;
    asm("fma.rn.f32x2 %0, %1, %2, %3;" : "=l"(d) : "l"(a), "l"(b), "l"(c));
    return d;
}
__device__ __forceinline__ ull pack2(float x, float y) {
    ull d;
    asm("mov.b64 %0, {%1, %2};" : "=l"(d) : "f"(x), "f"(y));
    return d;
}
__device__ __forceinline__ float2 unpack2(ull v) {
    float2 r;
    asm("mov.b64 {%0, %1}, %2;" : "=f"(r.x), "=f"(r.y) : "l"(v));
    return r;
}
__device__ __forceinline__ float tf32r(float x) {
    float y;
    asm("cvt.rna.tf32.f32 %0, %1;" : "=f"(y) : "f"(x));
    return y;
}
__device__ __forceinline__ void mma_tf32(float& c0, float& c1, float& c2, float& c3,
                                         unsigned a0, unsigned a1, unsigned a2, unsigned a3,
                                         unsigned b0, unsigned b1) {
    asm volatile("mma.sync.aligned.m16n8k8.row.col.f32.tf32.tf32.f32 "
                 "{%0,%1,%2,%3}, {%4,%5,%6,%7}, {%8,%9}, {%0,%1,%2,%3};"
                 : "+f"(c0), "+f"(c1), "+f"(c2), "+f"(c3)
                 : "r"(a0), "r"(a1), "r"(a2), "r"(a3), "r"(b0), "r"(b1));
}
__device__ __forceinline__ void cpa16(unsigned smem, const void* g) {
    asm volatile("cp.async.cg.shared.global [%0], [%1], 16;" :: "r"(smem), "l"(g));
}
#define CP_COMMIT() asm volatile("cp.async.commit_group;" ::: "memory")
#define CP_WAIT1()  asm volatile("cp.async.wait_group 1;" ::: "memory")
#define CP_WAIT0()  asm volatile("cp.async.wait_group 0;" ::: "memory")

// ---------------- scratch ----------------
__device__ __align__(16) float g_grouped[MM * AA * NSK * 5];
__device__ __align__(16) float g_v0[MM * 64 * AA];
__device__ __align__(16) float g_c1[MM * 96 * 63];
__device__ __align__(16) float g_c2[MM * 128 * 5];
__device__ __align__(16) float g_gx[MM * 256];
__device__ __align__(16) float g_wb[217 * 768];     // conv1 W fragment order (+1 ts pad)
__device__ __align__(16) float g_w3b[2048];         // pointnet W3 fragment order
__device__ __align__(16) float g_w2pb[512];         // pointnet W2 fragment order
__device__ __align__(16) float g_w2b[333056];       // conv2 W fragment order (+pad)
__device__ __align__(16) float g_wt3[640 * 64];     // [k][oc]

// ---------------- weight prep ----------------
__global__ void transpose_kernel(const float* __restrict__ w1,
                                 const float* __restrict__ w2,
                                 const float* __restrict__ w3,
                                 const float* __restrict__ pw2,
                                 const float* __restrict__ pw3) {
    int i = blockIdx.x * blockDim.x + threadIdx.x;
    if (i < 216 * 768) {
        int ts = i / 768;
        int r  = i % 768;
        int wn = r / 384;
        int r2 = r % 384;
        int lane = r2 / 12;
        int j = r2 % 12;
        int f = j >> 1, half = j & 1;
        int g = lane >> 2, tig = lane & 3;
        int k  = ts * 8 + tig + half * 4;
        int oc = wn * 48 + f * 8 + g;
        g_wb[i] = tf32r(w1[oc * 1728 + k]);
    } else if (i < 217 * 768) {
        g_wb[i] = 0.f;
    }
    if (i < 2048) {
        int kt = i >> 9;
        int r  = i & 511;
        int lane = r >> 4;
        int j = r & 15;
        int nf = j >> 1, half = j & 1;
        int g = lane >> 2, tig = lane & 3;
        int row = kt * 8 + tig + half * 4;
        int col = nf * 8 + g;
        g_w3b[i] = tf32r(pw3[row * 64 + col]);
    }
    if (i < 512) {
        int kt = i >> 8;
        int r  = i & 255;
        int lane = r >> 3;
        int j = r & 7;
        int nf = j >> 1, half = j & 1;
        int g = lane >> 2, tig = lane & 3;
        int k   = kt * 8 + tig + half * 4;
        int col = nf * 8 + g;
        g_w2pb[i] = tf32r(pw2[k * 32 + col]);
    }
    if (i < 331776) {
        int ts_wn = i >> 7;
        int r     = i & 127;
        int lane  = r >> 2;
        int j     = r & 3;
        int nf = j >> 1, half = j & 1;
        int g = lane >> 2, tig = lane & 3;
        int wn = ts_wn & 7;
        int ts = ts_wn >> 3;
        int k  = ts * 8 + tig + half * 4;
        int oc = wn * 16 + nf * 8 + g;
        g_w2b[i] = tf32r(w2[oc * 2592 + k]);
    } else if (i < 333056) {
        g_w2b[i] = 0.f;
    }
    if (i < 64 * 640) g_wt3[(i % 640) * 64 + (i / 640)] = w3[i];
}

// ---------------- KNN + group ----------------
__global__ __launch_bounds__(256) void knn_group_kernel(const float* __restrict__ x,
                                                        const float* __restrict__ g_loc) {
    int m = blockIdx.x;
    __shared__ float px[NPT], py[NPT], pz[NPT], p0[NPT], p1[NPT], pn2[NPT];
    int tid = threadIdx.x;
    if (tid < NPT) {
        const float* xp = x + (m * NPT + tid) * 5;
        float a = xp[0], b = xp[1], c = xp[2];
        px[tid] = a; py[tid] = b; pz[tid] = c;
        p0[tid] = xp[3]; p1[tid] = xp[4];
        pn2[tid] = a * a + b * b + c * c;
    }
    __syncthreads();
    if (tid >= AA) return;
    int aI = tid;
    int zi = aI / 25, rem = aI % 25, yi = rem / 5, xi = rem % 5;
    float ax = ((float)xi - 2.0f) * 0.2f + g_loc[m * 2 + 0];
    float ay = ((float)yi - 2.0f) * 0.2f + g_loc[m * 2 + 1];
    float az = (float)zi * 0.22f + 0.1f;
    float an2 = ax * ax + ay * ay + az * az;

    float bd[NSK]; int bix[NSK];
#pragma unroll
    for (int k = 0; k < NSK; k++) { bd[k] = 3.4e38f; bix[k] = 0; }
    for (int n = 0; n < NPT; n++) {
        float d = an2 - 2.0f * (ax * px[n] + ay * py[n] + az * pz[n]) + pn2[n];
        if (d < bd[NSK - 1]) {
            float cd = d; int ci = n;
#pragma unroll
            for (int k = 0; k < NSK; k++) {
                if (cd < bd[k]) {
                    float td = bd[k]; int ti = bix[k];
                    bd[k] = cd; bix[k] = ci; cd = td; ci = ti;
                }
            }
        }
    }
    float* gp = g_grouped + (m * AA + aI) * NSK * 5;
#pragma unroll
    for (int k = 0; k < NSK; k++) {
        int n = bix[k];
        gp[k * 5 + 0] = px[n] - ax;
        gp[k * 5 + 1] = py[n] - ay;
        gp[k * 5 + 2] = pz[n] - az;
        gp[k * 5 + 3] = p0[n];
        gp[k * 5 + 4] = p1[n];
    }
}

// ---------------- PointNet: layer1 scalar, layers 2+3 tensor-core ----------
__global__ __launch_bounds__(128) void pointnet_attn_kernel(
    const float* __restrict__ w1, const float* __restrict__ b1,
    const float* __restrict__ b2, const float* __restrict__ b3,
    const float* __restrict__ aw, const float* __restrict__ ab,
    float* __restrict__ out_attn) {
    __shared__ __align__(16) float sX[128 * 66];
    __shared__ __align__(16) float sw[256];
    float* sw1 = sw;
    float* sb1 = sw + 80;
    float* sb2 = sw + 96;
    float* sb3 = sw + 128;
    float* saw = sw + 192;
    int tid = threadIdx.x;
    for (int i = tid; i < 80; i += 128) sw1[i] = w1[i];
    if (tid < 16) sb1[tid] = b1[tid];
    if (tid < 32) sb2[tid] = b2[tid];
    if (tid < 64) sb3[tid] = b3[tid];
    if (tid < 64) saw[tid] = aw[tid];
    __syncthreads();
    float abv = ab[0];

    const float* gin = g_grouped + ((size_t)blockIdx.x * 128 + tid) * 5;
    float xin[5];
    xin[0] = gin[0]; xin[1] = gin[1]; xin[2] = gin[2]; xin[3] = gin[3]; xin[4] = gin[4];

    float h1[16];
    {
        ull a1[8];
#pragma unroll
        for (int p = 0; p < 8; p++) a1[p] = ((const ull*)sb1)[p];
#pragma unroll
        for (int i = 0; i < 5; i++) {
            ull hh = pack2(xin[i], xin[i]);
            const ulonglong2* wr = (const ulonglong2*)&sw1[i * 16];
#pragma unroll
            for (int q = 0; q < 4; q++) {
                ulonglong2 wv = wr[q];
                a1[2 * q]     = fma2(hh, wv.x, a1[2 * q]);
                a1[2 * q + 1] = fma2(hh, wv.y, a1[2 * q + 1]);
            }
        }
#pragma unroll
        for (int p = 0; p < 8; p++) {
            float2 v = unpack2(a1[p]);
            h1[2 * p] = fmaxf(v.x, 0.f); h1[2 * p + 1] = fmaxf(v.y, 0.f);
        }
    }
    {
        float* xr = sX + tid * 36;
#pragma unroll
        for (int j = 0; j < 16; j += 4) {
            float4 v;
            v.x = tf32r(h1[j]);     v.y = tf32r(h1[j + 1]);
            v.z = tf32r(h1[j + 2]); v.w = tf32r(h1[j + 3]);
            *(float4*)(xr + j) = v;
        }
    }
    __syncthreads();

    int warp = tid >> 5, lane = tid & 31, g = lane >> 2, tig = lane & 3;

    // ---- layer2 MMA: [128 x 16] @ [16 x 32] ----
    {
        unsigned b2f[2][4][2];
        {
            const float4* wb2 = (const float4*)g_w2pb;
#pragma unroll
            for (int kt = 0; kt < 2; kt++) {
                float4 v0 = wb2[kt * 64 + lane * 2];
                float4 v1 = wb2[kt * 64 + lane * 2 + 1];
                b2f[kt][0][0] = __float_as_uint(v0.x); b2f[kt][0][1] = __float_as_uint(v0.y);
                b2f[kt][1][0] = __float_as_uint(v0.z); b2f[kt][1][1] = __float_as_uint(v0.w);
                b2f[kt][2][0] = __float_as_uint(v1.x); b2f[kt][2][1] = __float_as_uint(v1.y);
                b2f[kt][3][0] = __float_as_uint(v1.z); b2f[kt][3][1] = __float_as_uint(v1.w);
            }
        }
        unsigned a2f[2][2][4];
#pragma unroll
        for (int mt = 0; mt < 2; mt++) {
            int r0 = warp * 32 + mt * 16 + g;
            const float* x0 = sX + r0 * 36;
            const float* x1 = sX + (r0 + 8) * 36;
#pragma unroll
            for (int kt = 0; kt < 2; kt++) {
                int c0 = kt * 8 + tig;
                a2f[mt][kt][0] = __float_as_uint(x0[c0]);
                a2f[mt][kt][1] = __float_as_uint(x1[c0]);
                a2f[mt][kt][2] = __float_as_uint(x0[c0 + 4]);
                a2f[mt][kt][3] = __float_as_uint(x1[c0 + 4]);
            }
        }
        float acc2[2][4][4];
#pragma unroll
        for (int mt = 0; mt < 2; mt++)
#pragma unroll
            for (int nf = 0; nf < 4; nf++)
#pragma unroll
                for (int j = 0; j < 4; j++) acc2[mt][nf][j] = 0.f;
#pragma unroll
        for (int mt = 0; mt < 2; mt++)
#pragma unroll
            for (int kt = 0; kt < 2; kt++)
#pragma unroll
                for (int nf = 0; nf < 4; nf++)
                    mma_tf32(acc2[mt][nf][0], acc2[mt][nf][1], acc2[mt][nf][2], acc2[mt][nf][3],
                             a2f[mt][kt][0], a2f[mt][kt][1], a2f[mt][kt][2], a2f[mt][kt][3],
                             b2f[kt][nf][0], b2f[kt][nf][1]);
        __syncthreads();
#pragma unroll
        for (int mt = 0; mt < 2; mt++) {
            int r0 = warp * 32 + mt * 16 + g;
#pragma unroll
            for (int nf = 0; nf < 4; nf++) {
                int c0 = nf * 8 + 2 * tig;
                float bb0 = sb2[c0], bb1 = sb2[c0 + 1];
                float2 v0 = make_float2(tf32r(fmaxf(acc2[mt][nf][0] + bb0, 0.f)),
                                        tf32r(fmaxf(acc2[mt][nf][1] + bb1, 0.f)));
                float2 v1 = make_float2(tf32r(fmaxf(acc2[mt][nf][2] + bb0, 0.f)),
                                        tf32r(fmaxf(acc2[mt][nf][3] + bb1, 0.f)));
                *(float2*)(sX + r0 * 36 + c0)       = v0;
                *(float2*)(sX + (r0 + 8) * 36 + c0) = v1;
            }
        }
    }
    __syncthreads();

    // ---- layer3 MMA: [128 x 32] @ [32 x 64] ----
    unsigned bf[4][8][2];
    {
        const float4* wb = (const float4*)g_w3b;
#pragma unroll
        for (int kt = 0; kt < 4; kt++) {
#pragma unroll
            for (int q = 0; q < 4; q++) {
                float4 v = wb[kt * 128 + lane * 4 + q];
                bf[kt][2 * q][0]     = __float_as_uint(v.x);
                bf[kt][2 * q][1]     = __float_as_uint(v.y);
                bf[kt][2 * q + 1][0] = __float_as_uint(v.z);
                bf[kt][2 * q + 1][1] = __float_as_uint(v.w);
            }
        }
    }
    float acc[2][8][4];
#pragma unroll
    for (int mt = 0; mt < 2; mt++)
#pragma unroll
        for (int nf = 0; nf < 8; nf++)
#pragma unroll
            for (int j = 0; j < 4; j++) acc[mt][nf][j] = 0.f;

#pragma unroll
    for (int mt = 0; mt < 2; mt++) {
        int r0 = (warp * 2 + mt) * 16 + g;
        const float* x0 = sX + r0 * 36;
        const float* x1 = sX + (r0 + 8) * 36;
#pragma unroll
        for (int kt = 0; kt < 4; kt++) {
            int c0 = kt * 8 + tig;
            unsigned a0 = __float_as_uint(x0[c0]);
            unsigned a1 = __float_as_uint(x1[c0]);
            unsigned a2 = __float_as_uint(x0[c0 + 4]);
            unsigned a3 = __float_as_uint(x1[c0 + 4]);
#pragma unroll
            for (int nf = 0; nf < 8; nf++)
                mma_tf32(acc[mt][nf][0], acc[mt][nf][1], acc[mt][nf][2], acc[mt][nf][3],
                         a0, a1, a2, a3, bf[kt][nf][0], bf[kt][nf][1]);
        }
    }
    __syncthreads();

#pragma unroll
    for (int mt = 0; mt < 2; mt++) {
        int r0 = (warp * 2 + mt) * 16 + g;
#pragma unroll
        for (int nf = 0; nf < 8; nf++) {
            int col = nf * 8 + 2 * tig;
            float bb0 = sb3[col], bb1 = sb3[col + 1];
            float2 v0 = make_float2(fmaxf(acc[mt][nf][0] + bb0, 0.f),
                                    fmaxf(acc[mt][nf][1] + bb1, 0.f));
            float2 v1 = make_float2(fmaxf(acc[mt][nf][2] + bb0, 0.f),
                                    fmaxf(acc[mt][nf][3] + bb1, 0.f));
            *(float2*)(sX + r0 * 66 + col)       = v0;
            *(float2*)(sX + (r0 + 8) * 66 + col) = v1;
        }
    }
    __syncthreads();

    float f[64];
    {
        const float* fr = sX + tid * 66;
#pragma unroll
        for (int c = 0; c < 64; c += 2) {
            float2 v = *(const float2*)(fr + c);
            f[c] = v.x; f[c + 1] = v.y;
        }
    }
    int k = tid & 7;
    float logit = abv;
#pragma unroll
    for (int c = 0; c < 64; c++) logit = fmaf(f[c], saw[c], logit);

    float mx = logit;
    mx = fmaxf(mx, __shfl_xor_sync(0xffffffffu, mx, 1));
    mx = fmaxf(mx, __shfl_xor_sync(0xffffffffu, mx, 2));
    mx = fmaxf(mx, __shfl_xor_sync(0xffffffffu, mx, 4));
    float e = expf(logit - mx);
    float s = e;
    s += __shfl_xor_sync(0xffffffffu, s, 1);
    s += __shfl_xor_sync(0xffffffffu, s, 2);
    s += __shfl_xor_sync(0xffffffffu, s, 4);
    float attn = e / s;
    out_attn[(size_t)blockIdx.x * 128 + tid] = attn;

#pragma unroll
    for (int c = 0; c < 64; c++) f[c] *= attn;

    bool kb0 = (k & 1) != 0, kb1 = (k & 2) != 0, kb2 = (k & 4) != 0;
    float r32[32];
#pragma unroll
    for (int h = 0; h < 4; h++) {
#pragma unroll
        for (int lo = 0; lo < 8; lo++) {
            float keep = kb0 ? f[(h * 2 + 1) * 8 + lo] : f[(h * 2) * 8 + lo];
            float send = kb0 ? f[(h * 2) * 8 + lo]     : f[(h * 2 + 1) * 8 + lo];
            r32[h * 8 + lo] = keep + __shfl_xor_sync(0xffffffffu, send, 1);
        }
    }
    float r16[16];
#pragma unroll
    for (int h = 0; h < 2; h++) {
#pragma unroll
        for (int lo = 0; lo < 8; lo++) {
            float keep = kb1 ? r32[(h * 2 + 1) * 8 + lo] : r32[(h * 2) * 8 + lo];
            float send = kb1 ? r32[(h * 2) * 8 + lo]     : r32[(h * 2 + 1) * 8 + lo];
            r16[h * 8 + lo] = keep + __shfl_xor_sync(0xffffffffu, send, 2);
        }
    }
    float r8[8];
#pragma unroll
    for (int lo = 0; lo < 8; lo++) {
        float keep = kb2 ? r16[8 + lo] : r16[lo];
        float send = kb2 ? r16[lo]     : r16[8 + lo];
        r8[lo] = keep + __shfl_xor_sync(0xffffffffu, send, 4);
    }

    int vox = blockIdx.x * 16 + (tid >> 3);
    int m = vox / AA, a = vox % AA;
    float* vbase = g_v0 + (size_t)m * 64 * AA + a;
#pragma unroll
    for (int lo = 0; lo < 8; lo++)
        vbase[(k * 8 + lo) * AA] = tf32r(r8[lo]);
}

// ---------------- conv1 via implicit GEMM, mma.sync tf32, 2 samples/block ----------------
// cp.async double-buffered 8-stage staging (8 ic per stage); B prefetch retained.
#define C1_E 1800
__global__ __launch_bounds__(256) void conv1_kernel(const float* __restrict__ bias) {
    __shared__ __align__(16) float sin[2][2 * C1_E];   // [buf][sample*C1_E]
    __shared__ int   ktbl[27];
    __shared__ float sbias[96];

    int tid = threadIdx.x;
    int warp = tid >> 5;
    int lane = tid & 31;
    int g   = lane >> 2;
    int tig = lane & 3;
    int warpM = warp & 3;
    int warpN = warp >> 2;
    int nb = warpN * 48;

    if (tid < 27) {
        int kz = tid / 9, r = tid % 9, ky = r / 3, kx = r % 3;
        ktbl[tid] = kz * 25 + ky * 5 + kx;
    }
    if (tid < 96) sbias[tid] = bias[tid];
    __syncthreads();   // ktbl ready before mainloop (copies don't touch it)

    int s_lo = warpM * 16 + g;
    int s_hi = s_lo + 8;
    int s_hic = (s_hi > 62) ? 62 : s_hi;
    int zlo = s_lo / 9, rlo = s_lo % 9;
    int solo = zlo * 25 + (rlo / 3) * 5 + (rlo % 3);
    int zhi = s_hic / 9, rhi = s_hic % 9;
    int sohi = zhi * 25 + (rhi / 3) * 5 + (rhi % 3);

    float acc[2][6][4];
#pragma unroll
    for (int sm = 0; sm < 2; sm++)
#pragma unroll
        for (int f = 0; f < 6; f++)
#pragma unroll
            for (int j = 0; j < 4; j++) acc[sm][f][j] = 0.f;

    const float* pWB = g_wb + warpN * 384 + lane * 12;
    float4 q0 = *(const float4*)(pWB);
    float4 q1 = *(const float4*)(pWB + 4);
    float4 q2 = *(const float4*)(pWB + 8);
    pWB += 768;

    const float* src0 = g_v0 + (size_t)(2 * blockIdx.x) * 14400;
    const float* src1 = src0 + 14400;
    unsigned sbase = (unsigned)__cvta_generic_to_shared(&sin[0][0]);

    // issue stage 0
    {
        unsigned d = sbase;
        const float* s0 = src0;
        const float* s1 = src1;
        for (int i = tid; i < 450; i += 256) {
            cpa16(d + i * 16, s0 + i * 4);
            cpa16(d + C1_E * 4 + i * 16, s1 + i * 4);
        }
        CP_COMMIT();
    }

    for (int st = 0; st < 8; st++) {
        if (st < 7) {
            unsigned d = sbase + ((st + 1) & 1) * (2 * C1_E * 4);
            const float* s0 = src0 + (st + 1) * C1_E;
            const float* s1 = src1 + (st + 1) * C1_E;
            for (int i = tid; i < 450; i += 256) {
                cpa16(d + i * 16, s0 + i * 4);
                cpa16(d + C1_E * 4 + i * 16, s1 + i * 4);
            }
            CP_COMMIT();
            CP_WAIT1();
        } else {
            CP_WAIT0();
        }
        __syncthreads();
        const float* buf = sin[st & 1];

        int rr0 = tig, rr1 = tig + 4;
        int icoff0 = 0, icoff1 = 0;
        for (int ts = 0; ts < 27; ts++) {
            float4 n0 = *(const float4*)(pWB);
            float4 n1 = *(const float4*)(pWB + 4);
            float4 n2 = *(const float4*)(pWB + 8);
            pWB += 768;
            int kt0 = ktbl[rr0];
            int kt1 = ktbl[rr1];
            int i00 = icoff0 + kt0 + solo;
            int i01 = icoff0 + kt0 + sohi;
            int i10 = icoff1 + kt1 + solo;
            int i11 = icoff1 + kt1 + sohi;
            unsigned a0 = __float_as_uint(buf[i00]);
            unsigned a1 = __float_as_uint(buf[i01]);
            unsigned a2 = __float_as_uint(buf[i10]);
            unsigned a3 = __float_as_uint(buf[i11]);
            unsigned b0 = __float_as_uint(buf[C1_E + i00]);
            unsigned b1 = __float_as_uint(buf[C1_E + i01]);
            unsigned b2 = __float_as_uint(buf[C1_E + i10]);
            unsigned b3 = __float_as_uint(buf[C1_E + i11]);
            rr0 += 8; if (rr0 >= 27) { rr0 -= 27; icoff0 += 225; }
            rr1 += 8; if (rr1 >= 27) { rr1 -= 27; icoff1 += 225; }
            mma_tf32(acc[0][0][0], acc[0][0][1], acc[0][0][2], acc[0][0][3], a0, a1, a2, a3,
                     __float_as_uint(q0.x), __float_as_uint(q0.y));
            mma_tf32(acc[1][0][0], acc[1][0][1], acc[1][0][2], acc[1][0][3], b0, b1, b2, b3,
                     __float_as_uint(q0.x), __float_as_uint(q0.y));
            mma_tf32(acc[0][1][0], acc[0][1][1], acc[0][1][2], acc[0][1][3], a0, a1, a2, a3,
                     __float_as_uint(q0.z), __float_as_uint(q0.w));
            mma_tf32(acc[1][1][0], acc[1][1][1], acc[1][1][2], acc[1][1][3], b0, b1, b2, b3,
                     __float_as_uint(q0.z), __float_as_uint(q0.w));
            mma_tf32(acc[0][2][0], acc[0][2][1], acc[0][2][2], acc[0][2][3], a0, a1, a2, a3,
                     __float_as_uint(q1.x), __float_as_uint(q1.y));
            mma_tf32(acc[1][2][0], acc[1][2][1], acc[1][2][2], acc[1][2][3], b0, b1, b2, b3,
                     __float_as_uint(q1.x), __float_as_uint(q1.y));
            mma_tf32(acc[0][3][0], acc[0][3][1], acc[0][3][2], acc[0][3][3], a0, a1, a2, a3,
                     __float_as_uint(q1.z), __float_as_uint(q1.w));
            mma_tf32(acc[1][3][0], acc[1][3][1], acc[1][3][2], acc[1][3][3], b0, b1, b2, b3,
                     __float_as_uint(q1.z), __float_as_uint(q1.w));
            mma_tf32(acc[0][4][0], acc[0][4][1], acc[0][4][2], acc[0][4][3], a0, a1, a2, a3,
                     __float_as_uint(q2.x), __float_as_uint(q2.y));
            mma_tf32(acc[1][4][0], acc[1][4][1], acc[1][4][2], acc[1][4][3], b0, b1, b2, b3,
                     __float_as_uint(q2.x), __float_as_uint(q2.y));
            mma_tf32(acc[0][5][0], acc[0][5][1], acc[0][5][2], acc[0][5][3], a0, a1, a2, a3,
                     __float_as_uint(q2.z), __float_as_uint(q2.w));
            mma_tf32(acc[1][5][0], acc[1][5][1], acc[1][5][2], acc[1][5][3], b0, b1, b2, b3,
                     __float_as_uint(q2.z), __float_as_uint(q2.w));
            q0 = n0; q1 = n1; q2 = n2;
        }
        __syncthreads();
    }

#pragma unroll
    for (int sm = 0; sm < 2; sm++) {
        float* outb = g_c1 + (size_t)(2 * blockIdx.x + sm) * 96 * 63;
#pragma unroll
        for (int f = 0; f < 6; f++) {
            int oc0 = nb + f * 8 + 2 * tig;
            int oc1 = oc0 + 1;
            float b0 = sbias[oc0], b1 = sbias[oc1];
            outb[oc0 * 63 + s_lo] = tf32r(fmaxf(acc[sm][f][0] + b0, 0.f));
            outb[oc1 * 63 + s_lo] = tf32r(fmaxf(acc[sm][f][1] + b1, 0.f));
            if (s_hi < 63) {
                outb[oc0 * 63 + s_hi] = tf32r(fmaxf(acc[sm][f][2] + b0, 0.f));
                outb[oc1 * 63 + s_hi] = tf32r(fmaxf(acc[sm][f][3] + b1, 0.f));
            }
        }
    }
}

// ---------------- conv2 via implicit GEMM, mma.sync tf32 (2-chunk cp.async) ----------------
__global__ __launch_bounds__(256) void conv2_kernel(const float* __restrict__ bias) {
    __shared__ __align__(16) float sin[12096];   // 2 x 96 x 63
    __shared__ int   ktbl[27];
    __shared__ float sbias[128];

    int tid = threadIdx.x;
    int warp = tid >> 5;
    int lane = tid & 31;
    int g   = lane >> 2;
    int tig = lane & 3;

    if (tid < 27) {
        int kz = tid / 9, r = tid % 9, ky = r / 3, kx = r % 3;
        ktbl[tid] = kz * 9 + ky * 3 + kx;
    }
    if (tid < 128) sbias[tid] = bias[tid];
    __syncthreads();

    const float* src = g_c1 + (size_t)blockIdx.x * 12096;
    unsigned sbase = (unsigned)__cvta_generic_to_shared(sin);
    // chunk A: ic<48 for both samples -> f4 [0,756) and [1512,2268)
    for (int i = tid; i < 756; i += 256) {
        cpa16(sbase + i * 16, src + i * 4);
        cpa16(sbase + (1512 + i) * 16, src + (1512 + i) * 4);
    }
    CP_COMMIT();
    // chunk B: ic>=48 -> f4 [756,1512) and [2268,3024)
    for (int i = tid; i < 756; i += 256) {
        cpa16(sbase + (756 + i) * 16, src + (756 + i) * 4);
        cpa16(sbase + (2268 + i) * 16, src + (2268 + i) * 4);
    }
    CP_COMMIT();

    int sub0 = (g < 5) ? 0 : 1;
    int z0   = (g < 5) ? g : g - 5;
    int base0 = sub0 * 6048 + z0 * 9;
    bool p1 = (g < 2);
    int base1 = 6048 + (g + 3) * 9;

    float acc[2][4];
#pragma unroll
    for (int nf = 0; nf < 2; nf++)
#pragma unroll
        for (int j = 0; j < 4; j++) acc[nf][j] = 0.f;

    const float* pWB = g_w2b + warp * 128 + lane * 4;
    float4 q = *(const float4*)pWB;
    pWB += 1024;

    CP_WAIT1();
    __syncthreads();

    int rr0 = tig, rr1 = tig + 4;
    int icoff0 = 0, icoff1 = 0;
    for (int phase = 0; phase < 2; phase++) {
        int tsN = (phase == 0) ? 162 : 324;
        for (int ts = (phase == 0) ? 0 : 162; ts < tsN; ts++) {
            float4 n = *(const float4*)pWB;
            pWB += 1024;
            int o0 = ktbl[rr0];
            int o1 = ktbl[rr1];
            unsigned a0 = __float_as_uint(sin[base0 + icoff0 + o0]);
            unsigned a1 = p1 ? __float_as_uint(sin[base1 + icoff0 + o0]) : 0u;
            unsigned a2 = __float_as_uint(sin[base0 + icoff1 + o1]);
            unsigned a3 = p1 ? __float_as_uint(sin[base1 + icoff1 + o1]) : 0u;
            rr0 += 8; if (rr0 >= 27) { rr0 -= 27; icoff0 += 63; }
            rr1 += 8; if (rr1 >= 27) { rr1 -= 27; icoff1 += 63; }
            mma_tf32(acc[0][0], acc[0][1], acc[0][2], acc[0][3], a0, a1, a2, a3,
                     __float_as_uint(q.x), __float_as_uint(q.y));
            mma_tf32(acc[1][0], acc[1][1], acc[1][2], acc[1][3], a0, a1, a2, a3,
                     __float_as_uint(q.z), __float_as_uint(q.w));
            q = n;
        }
        if (phase == 0) {
            CP_WAIT0();
            __syncthreads();
        }
    }

    int m0 = blockIdx.x * 2 + sub0;
    int m1 = blockIdx.x * 2 + 1;
#pragma unroll
    for (int nf = 0; nf < 2; nf++) {
        int oc0 = warp * 16 + nf * 8 + 2 * tig;
        int oc1 = oc0 + 1;
        float b0 = sbias[oc0], b1 = sbias[oc1];
        g_c2[(m0 * 128 + oc0) * 5 + z0] = fmaxf(acc[nf][0] + b0, 0.f);
        g_c2[(m0 * 128 + oc1) * 5 + z0] = fmaxf(acc[nf][1] + b1, 0.f);
        if (p1) {
            g_c2[(m1 * 128 + oc0) * 5 + (g + 3)] = fmaxf(acc[nf][2] + b0, 0.f);
            g_c2[(m1 * 128 + oc1) * 5 + (g + 3)] = fmaxf(acc[nf][3] + b1, 0.f);
        }
    }
}

// ---------------- fused conv3 + gates_x ----------------
__global__ __launch_bounds__(256) void vec_kernel(const float* __restrict__ b3,
                                                  const float* __restrict__ wi,
                                                  const float* __restrict__ lb) {
    int m = blockIdx.x; int tid = threadIdx.x;
    __shared__ float sin[640];
    __shared__ float sp[256];
    __shared__ float sv[64];
    const float* src = g_c2 + m * 640;
    for (int i = tid; i < 640; i += 256) sin[i] = src[i];
    __syncthreads();
    {
        int q = tid >> 6;
        int j = tid & 63;
        float acc = 0.f;
        int base = q * 160;
#pragma unroll 8
        for (int i = 0; i < 160; i++)
            acc = fmaf(sin[base + i], g_wt3[(base + i) * 64 + j], acc);
        sp[tid] = acc;
    }
    __syncthreads();
    if (tid < 64)
        sv[tid] = ((sp[tid] + sp[64 + tid]) + (sp[128 + tid] + sp[192 + tid])) + b3[tid];
    __syncthreads();
    float acc = lb[tid];
#pragma unroll
    for (int i = 0; i < 64; i++) acc = fmaf(sv[i], wi[i * 256 + tid], acc);
    g_gx[m * 256 + tid] = acc;
}

// ---------------- LSTM scan ----------------
__device__ __forceinline__ float sigmoidf_(float x) { return 1.0f / (1.0f + expf(-x)); }

__global__ __launch_bounds__(256) void lstm_kernel(const float* __restrict__ h0,
                                                   const float* __restrict__ c0,
                                                   const float* __restrict__ wh,
                                                   float* __restrict__ out_avec,
                                                   float* __restrict__ out_hn,
                                                   float* __restrict__ out_cn) {
    int b = blockIdx.x; int j = threadIdx.x;
    __shared__ float sh[64], sc[64], sg[256];
    float whreg[64];
#pragma unroll
    for (int i = 0; i < 64; i++) whreg[i] = wh[i * 256 + j];
    if (j < 64) { sh[j] = h0[b * 64 + j]; sc[j] = c0[b * 64 + j]; }
    __syncthreads();
    for (int t = 0; t < 64; t++) {
        float acc = g_gx[(b * 64 + t) * 256 + j];
#pragma unroll
        for (int i = 0; i < 64; i++) acc = fmaf(sh[i], whreg[i], acc);
        sg[j] = acc;
        __syncthreads();
        if (j < 64) {
            float ig = sigmoidf_(sg[j]);
            float fg = sigmoidf_(sg[64 + j]);
            float gg = tanhf(sg[128 + j]);
            float og = sigmoidf_(sg[192 + j]);
            float c = fg * sc[j] + ig * gg;
            float h = og * tanhf(c);
            sc[j] = c; sh[j] = h;
            out_avec[(b * 64 + t) * 64 + j] = h;
        }
        __syncthreads();
    }
    if (j < 64) { out_hn[b * 64 + j] = sh[j]; out_cn[b * 64 + j] = sc[j]; }
}

// ---------------- launch ----------------
extern "C" void kernel_launch(void* const* d_in, const int* in_sizes, int n_in,
                              void* d_out, int out_size) {
    (void)in_sizes; (void)n_in; (void)out_size;
    const float* x       = (const float*)d_in[0];
    const float* g_loc   = (const float*)d_in[1];
    const float* h0      = (const float*)d_in[2];
    const float* c0      = (const float*)d_in[3];
    const float* pn_w1   = (const float*)d_in[4];
    const float* pn_b1   = (const float*)d_in[5];
    const float* pn_w2   = (const float*)d_in[6];
    const float* pn_b2   = (const float*)d_in[7];
    const float* pn_w3   = (const float*)d_in[8];
    const float* pn_b3   = (const float*)d_in[9];
    const float* attn_w  = (const float*)d_in[10];
    const float* attn_b  = (const float*)d_in[11];
    const float* vx_w1   = (const float*)d_in[12];
    const float* vx_b1   = (const float*)d_in[13];
    const float* vx_w2   = (const float*)d_in[14];
    const float* vx_b2   = (const float*)d_in[15];
    const float* vx_w3   = (const float*)d_in[16];
    const float* vx_b3   = (const float*)d_in[17];
    const float* lstm_wi = (const float*)d_in[18];
    const float* lstm_wh = (const float*)d_in[19];
    const float* lstm_b  = (const float*)d_in[20];

    float* out      = (float*)d_out;
    float* out_avec = out;
    float* out_attn = out + 65536;
    float* out_hn   = out + 65536 + 1843200;
    float* out_cn   = out_hn + 1024;

    transpose_kernel<<<1302, 256>>>(vx_w1, vx_w2, vx_w3, pn_w2, pn_w3);
    knn_group_kernel<<<1024, 256>>>(x, g_loc);
    pointnet_attn_kernel<<<14400, 128>>>(pn_w1, pn_b1, pn_b2,
                                         pn_b3, attn_w, attn_b, out_attn);
    conv1_kernel<<<512, 256>>>(vx_b1);
    conv2_kernel<<<512, 256>>>(vx_b2);
    vec_kernel<<<1024, 256>>>(vx_b3, lstm_wi, lstm_b);
    lstm_kernel<<<16, 256>>>(h0, c0, lstm_wh, out_avec, out_hn, out_cn);
}

// round 16
// speedup vs baseline: 1.0859x; 1.0859x over previous
#include <cuda_runtime.h>
#include <math.h>

#define MM 1024
#define NPT 128
#define AA 225
#define NSK 8

typedef unsigned long long ull;

__device__ __forceinline__ ull fma2(ull a, ull b, ull c) {
    ull d;
    asm("fma.rn.f32x2 %0, %1, %2, %3;" : "=l"(d) : "l"(a), "l"(b), "l"(c));
    return d;
}
__device__ __forceinline__ ull pack2(float x, float y) {
    ull d;
    asm("mov.b64 %0, {%1, %2};" : "=l"(d) : "f"(x), "f"(y));
    return d;
}
__device__ __forceinline__ float2 unpack2(ull v) {
    float2 r;
    asm("mov.b64 {%0, %1}, %2;" : "=f"(r.x), "=f"(r.y) : "l"(v));
    return r;
}
__device__ __forceinline__ float tf32r(float x) {
    float y;
    asm("cvt.rna.tf32.f32 %0, %1;" : "=f"(y) : "f"(x));
    return y;
}
__device__ __forceinline__ void mma_tf32(float& c0, float& c1, float& c2, float& c3,
                                         unsigned a0, unsigned a1, unsigned a2, unsigned a3,
                                         unsigned b0, unsigned b1) {
    asm volatile("mma.sync.aligned.m16n8k8.row.col.f32.tf32.tf32.f32 "
                 "{%0,%1,%2,%3}, {%4,%5,%6,%7}, {%8,%9}, {%0,%1,%2,%3};"
                 : "+f"(c0), "+f"(c1), "+f"(c2), "+f"(c3)
                 : "r"(a0), "r"(a1), "r"(a2), "r"(a3), "r"(b0), "r"(b1));
}

// ---------------- scratch ----------------
__device__ __align__(16) float g_grouped[MM * AA * NSK * 5];
__device__ __align__(16) float g_v0[MM * 64 * AA];
__device__ __align__(16) float g_c1[MM * 96 * 63];
__device__ __align__(16) float g_c2[MM * 128 * 5];
__device__ __align__(16) float g_gx[MM * 256];
__device__ __align__(16) float g_wb[217 * 768];     // conv1 W fragment order (+1 ts pad)
__device__ __align__(16) float g_w3b[2048];         // pointnet W3 fragment order
__device__ __align__(16) float g_w2pb[512];         // pointnet W2 fragment order
__device__ __align__(16) float g_w2b[333056];       // conv2 W fragment order (+pad)
__device__ __align__(16) float g_wt3[640 * 64];     // [k][oc]

// ---------------- fused prep: blocks <1024 do KNN; rest pack weights ----------------
__global__ __launch_bounds__(256) void prep_kernel(
    const float* __restrict__ x, const float* __restrict__ g_loc,
    const float* __restrict__ w1, const float* __restrict__ w2,
    const float* __restrict__ w3, const float* __restrict__ pw2,
    const float* __restrict__ pw3) {
    int tid = threadIdx.x;
    if (blockIdx.x >= 1024) {
        int i = (blockIdx.x - 1024) * 256 + tid;
        if (i < 216 * 768) {
            int ts = i / 768;
            int r  = i % 768;
            int wn = r / 384;
            int r2 = r % 384;
            int lane = r2 / 12;
            int j = r2 % 12;
            int f = j >> 1, half = j & 1;
            int g = lane >> 2, tig = lane & 3;
            int k  = ts * 8 + tig + half * 4;
            int oc = wn * 48 + f * 8 + g;
            g_wb[i] = tf32r(w1[oc * 1728 + k]);
        } else if (i < 217 * 768) {
            g_wb[i] = 0.f;
        }
        if (i < 2048) {
            int kt = i >> 9;
            int r  = i & 511;
            int lane = r >> 4;
            int j = r & 15;
            int nf = j >> 1, half = j & 1;
            int g = lane >> 2, tig = lane & 3;
            int row = kt * 8 + tig + half * 4;
            int col = nf * 8 + g;
            g_w3b[i] = tf32r(pw3[row * 64 + col]);
        }
        if (i < 512) {
            int kt = i >> 8;
            int r  = i & 255;
            int lane = r >> 3;
            int j = r & 7;
            int nf = j >> 1, half = j & 1;
            int g = lane >> 2, tig = lane & 3;
            int k   = kt * 8 + tig + half * 4;
            int col = nf * 8 + g;
            g_w2pb[i] = tf32r(pw2[k * 32 + col]);
        }
        if (i < 331776) {
            int ts_wn = i >> 7;
            int r     = i & 127;
            int lane  = r >> 2;
            int j     = r & 3;
            int nf = j >> 1, half = j & 1;
            int g = lane >> 2, tig = lane & 3;
            int wn = ts_wn & 7;
            int ts = ts_wn >> 3;
            int k  = ts * 8 + tig + half * 4;
            int oc = wn * 16 + nf * 8 + g;
            g_w2b[i] = tf32r(w2[oc * 2592 + k]);
        } else if (i < 333056) {
            g_w2b[i] = 0.f;
        }
        if (i < 64 * 640) g_wt3[(i % 640) * 64 + (i / 640)] = w3[i];
        return;
    }
    // ---- KNN branch ----
    int m = blockIdx.x;
    __shared__ float px[NPT], py[NPT], pz[NPT], p0[NPT], p1[NPT], pn2[NPT];
    if (tid < NPT) {
        const float* xp = x + (m * NPT + tid) * 5;
        float a = xp[0], b = xp[1], c = xp[2];
        px[tid] = a; py[tid] = b; pz[tid] = c;
        p0[tid] = xp[3]; p1[tid] = xp[4];
        pn2[tid] = a * a + b * b + c * c;
    }
    __syncthreads();
    if (tid >= AA) return;
    int aI = tid;
    int zi = aI / 25, rem = aI % 25, yi = rem / 5, xi = rem % 5;
    float ax = ((float)xi - 2.0f) * 0.2f + g_loc[m * 2 + 0];
    float ay = ((float)yi - 2.0f) * 0.2f + g_loc[m * 2 + 1];
    float az = (float)zi * 0.22f + 0.1f;
    float an2 = ax * ax + ay * ay + az * az;

    float bd[NSK]; int bix[NSK];
#pragma unroll
    for (int k = 0; k < NSK; k++) { bd[k] = 3.4e38f; bix[k] = 0; }
    for (int n = 0; n < NPT; n++) {
        float d = an2 - 2.0f * (ax * px[n] + ay * py[n] + az * pz[n]) + pn2[n];
        if (d < bd[NSK - 1]) {
            float cd = d; int ci = n;
#pragma unroll
            for (int k = 0; k < NSK; k++) {
                if (cd < bd[k]) {
                    float td = bd[k]; int ti = bix[k];
                    bd[k] = cd; bix[k] = ci; cd = td; ci = ti;
                }
            }
        }
    }
    float* gp = g_grouped + (m * AA + aI) * NSK * 5;
#pragma unroll
    for (int k = 0; k < NSK; k++) {
        int n = bix[k];
        gp[k * 5 + 0] = px[n] - ax;
        gp[k * 5 + 1] = py[n] - ay;
        gp[k * 5 + 2] = pz[n] - az;
        gp[k * 5 + 3] = p0[n];
        gp[k * 5 + 4] = p1[n];
    }
}

// ---------------- PointNet: layer1 scalar, layers 2+3 tensor-core ----------
__global__ __launch_bounds__(128) void pointnet_attn_kernel(
    const float* __restrict__ w1, const float* __restrict__ b1,
    const float* __restrict__ b2, const float* __restrict__ b3,
    const float* __restrict__ aw, const float* __restrict__ ab,
    float* __restrict__ out_attn) {
    __shared__ __align__(16) float sX[128 * 66];
    __shared__ __align__(16) float sw[256];
    float* sw1 = sw;
    float* sb1 = sw + 80;
    float* sb2 = sw + 96;
    float* sb3 = sw + 128;
    float* saw = sw + 192;
    int tid = threadIdx.x;
    for (int i = tid; i < 80; i += 128) sw1[i] = w1[i];
    if (tid < 16) sb1[tid] = b1[tid];
    if (tid < 32) sb2[tid] = b2[tid];
    if (tid < 64) sb3[tid] = b3[tid];
    if (tid < 64) saw[tid] = aw[tid];
    __syncthreads();
    float abv = ab[0];

    const float* gin = g_grouped + ((size_t)blockIdx.x * 128 + tid) * 5;
    float xin[5];
    xin[0] = gin[0]; xin[1] = gin[1]; xin[2] = gin[2]; xin[3] = gin[3]; xin[4] = gin[4];

    float h1[16];
    {
        ull a1[8];
#pragma unroll
        for (int p = 0; p < 8; p++) a1[p] = ((const ull*)sb1)[p];
#pragma unroll
        for (int i = 0; i < 5; i++) {
            ull hh = pack2(xin[i], xin[i]);
            const ulonglong2* wr = (const ulonglong2*)&sw1[i * 16];
#pragma unroll
            for (int q = 0; q < 4; q++) {
                ulonglong2 wv = wr[q];
                a1[2 * q]     = fma2(hh, wv.x, a1[2 * q]);
                a1[2 * q + 1] = fma2(hh, wv.y, a1[2 * q + 1]);
            }
        }
#pragma unroll
        for (int p = 0; p < 8; p++) {
            float2 v = unpack2(a1[p]);
            h1[2 * p] = fmaxf(v.x, 0.f); h1[2 * p + 1] = fmaxf(v.y, 0.f);
        }
    }
    {
        float* xr = sX + tid * 36;
#pragma unroll
        for (int j = 0; j < 16; j += 4) {
            float4 v;
            v.x = tf32r(h1[j]);     v.y = tf32r(h1[j + 1]);
            v.z = tf32r(h1[j + 2]); v.w = tf32r(h1[j + 3]);
            *(float4*)(xr + j) = v;
        }
    }
    __syncthreads();

    int warp = tid >> 5, lane = tid & 31, g = lane >> 2, tig = lane & 3;

    // ---- layer2 MMA: [128 x 16] @ [16 x 32] ----
    {
        unsigned b2f[2][4][2];
        {
            const float4* wb2 = (const float4*)g_w2pb;
#pragma unroll
            for (int kt = 0; kt < 2; kt++) {
                float4 v0 = wb2[kt * 64 + lane * 2];
                float4 v1 = wb2[kt * 64 + lane * 2 + 1];
                b2f[kt][0][0] = __float_as_uint(v0.x); b2f[kt][0][1] = __float_as_uint(v0.y);
                b2f[kt][1][0] = __float_as_uint(v0.z); b2f[kt][1][1] = __float_as_uint(v0.w);
                b2f[kt][2][0] = __float_as_uint(v1.x); b2f[kt][2][1] = __float_as_uint(v1.y);
                b2f[kt][3][0] = __float_as_uint(v1.z); b2f[kt][3][1] = __float_as_uint(v1.w);
            }
        }
        unsigned a2f[2][2][4];
#pragma unroll
        for (int mt = 0; mt < 2; mt++) {
            int r0 = warp * 32 + mt * 16 + g;
            const float* x0 = sX + r0 * 36;
            const float* x1 = sX + (r0 + 8) * 36;
#pragma unroll
            for (int kt = 0; kt < 2; kt++) {
                int c0 = kt * 8 + tig;
                a2f[mt][kt][0] = __float_as_uint(x0[c0]);
                a2f[mt][kt][1] = __float_as_uint(x1[c0]);
                a2f[mt][kt][2] = __float_as_uint(x0[c0 + 4]);
                a2f[mt][kt][3] = __float_as_uint(x1[c0 + 4]);
            }
        }
        float acc2[2][4][4];
#pragma unroll
        for (int mt = 0; mt < 2; mt++)
#pragma unroll
            for (int nf = 0; nf < 4; nf++)
#pragma unroll
                for (int j = 0; j < 4; j++) acc2[mt][nf][j] = 0.f;
#pragma unroll
        for (int mt = 0; mt < 2; mt++)
#pragma unroll
            for (int kt = 0; kt < 2; kt++)
#pragma unroll
                for (int nf = 0; nf < 4; nf++)
                    mma_tf32(acc2[mt][nf][0], acc2[mt][nf][1], acc2[mt][nf][2], acc2[mt][nf][3],
                             a2f[mt][kt][0], a2f[mt][kt][1], a2f[mt][kt][2], a2f[mt][kt][3],
                             b2f[kt][nf][0], b2f[kt][nf][1]);
        __syncthreads();
#pragma unroll
        for (int mt = 0; mt < 2; mt++) {
            int r0 = warp * 32 + mt * 16 + g;
#pragma unroll
            for (int nf = 0; nf < 4; nf++) {
                int c0 = nf * 8 + 2 * tig;
                float bb0 = sb2[c0], bb1 = sb2[c0 + 1];
                float2 v0 = make_float2(tf32r(fmaxf(acc2[mt][nf][0] + bb0, 0.f)),
                                        tf32r(fmaxf(acc2[mt][nf][1] + bb1, 0.f)));
                float2 v1 = make_float2(tf32r(fmaxf(acc2[mt][nf][2] + bb0, 0.f)),
                                        tf32r(fmaxf(acc2[mt][nf][3] + bb1, 0.f)));
                *(float2*)(sX + r0 * 36 + c0)       = v0;
                *(float2*)(sX + (r0 + 8) * 36 + c0) = v1;
            }
        }
    }
    __syncthreads();

    // ---- layer3 MMA: [128 x 32] @ [32 x 64] ----
    unsigned bf[4][8][2];
    {
        const float4* wb = (const float4*)g_w3b;
#pragma unroll
        for (int kt = 0; kt < 4; kt++) {
#pragma unroll
            for (int q = 0; q < 4; q++) {
                float4 v = wb[kt * 128 + lane * 4 + q];
                bf[kt][2 * q][0]     = __float_as_uint(v.x);
                bf[kt][2 * q][1]     = __float_as_uint(v.y);
                bf[kt][2 * q + 1][0] = __float_as_uint(v.z);
                bf[kt][2 * q + 1][1] = __float_as_uint(v.w);
            }
        }
    }
    float acc[2][8][4];
#pragma unroll
    for (int mt = 0; mt < 2; mt++)
#pragma unroll
        for (int nf = 0; nf < 8; nf++)
#pragma unroll
            for (int j = 0; j < 4; j++) acc[mt][nf][j] = 0.f;

#pragma unroll
    for (int mt = 0; mt < 2; mt++) {
        int r0 = (warp * 2 + mt) * 16 + g;
        const float* x0 = sX + r0 * 36;
        const float* x1 = sX + (r0 + 8) * 36;
#pragma unroll
        for (int kt = 0; kt < 4; kt++) {
            int c0 = kt * 8 + tig;
            unsigned a0 = __float_as_uint(x0[c0]);
            unsigned a1 = __float_as_uint(x1[c0]);
            unsigned a2 = __float_as_uint(x0[c0 + 4]);
            unsigned a3 = __float_as_uint(x1[c0 + 4]);
#pragma unroll
            for (int nf = 0; nf < 8; nf++)
                mma_tf32(acc[mt][nf][0], acc[mt][nf][1], acc[mt][nf][2], acc[mt][nf][3],
                         a0, a1, a2, a3, bf[kt][nf][0], bf[kt][nf][1]);
        }
    }
    __syncthreads();

#pragma unroll
    for (int mt = 0; mt < 2; mt++) {
        int r0 = (warp * 2 + mt) * 16 + g;
#pragma unroll
        for (int nf = 0; nf < 8; nf++) {
            int col = nf * 8 + 2 * tig;
            float bb0 = sb3[col], bb1 = sb3[col + 1];
            float2 v0 = make_float2(fmaxf(acc[mt][nf][0] + bb0, 0.f),
                                    fmaxf(acc[mt][nf][1] + bb1, 0.f));
            float2 v1 = make_float2(fmaxf(acc[mt][nf][2] + bb0, 0.f),
                                    fmaxf(acc[mt][nf][3] + bb1, 0.f));
            *(float2*)(sX + r0 * 66 + col)       = v0;
            *(float2*)(sX + (r0 + 8) * 66 + col) = v1;
        }
    }
    __syncthreads();

    float f[64];
    {
        const float* fr = sX + tid * 66;
#pragma unroll
        for (int c = 0; c < 64; c += 2) {
            float2 v = *(const float2*)(fr + c);
            f[c] = v.x; f[c + 1] = v.y;
        }
    }
    int k = tid & 7;
    float logit = abv;
#pragma unroll
    for (int c = 0; c < 64; c++) logit = fmaf(f[c], saw[c], logit);

    float mx = logit;
    mx = fmaxf(mx, __shfl_xor_sync(0xffffffffu, mx, 1));
    mx = fmaxf(mx, __shfl_xor_sync(0xffffffffu, mx, 2));
    mx = fmaxf(mx, __shfl_xor_sync(0xffffffffu, mx, 4));
    float e = expf(logit - mx);
    float s = e;
    s += __shfl_xor_sync(0xffffffffu, s, 1);
    s += __shfl_xor_sync(0xffffffffu, s, 2);
    s += __shfl_xor_sync(0xffffffffu, s, 4);
    float attn = e / s;
    out_attn[(size_t)blockIdx.x * 128 + tid] = attn;

#pragma unroll
    for (int c = 0; c < 64; c++) f[c] *= attn;

    bool kb0 = (k & 1) != 0, kb1 = (k & 2) != 0, kb2 = (k & 4) != 0;
    float r32[32];
#pragma unroll
    for (int h = 0; h < 4; h++) {
#pragma unroll
        for (int lo = 0; lo < 8; lo++) {
            float keep = kb0 ? f[(h * 2 + 1) * 8 + lo] : f[(h * 2) * 8 + lo];
            float send = kb0 ? f[(h * 2) * 8 + lo]     : f[(h * 2 + 1) * 8 + lo];
            r32[h * 8 + lo] = keep + __shfl_xor_sync(0xffffffffu, send, 1);
        }
    }
    float r16[16];
#pragma unroll
    for (int h = 0; h < 2; h++) {
#pragma unroll
        for (int lo = 0; lo < 8; lo++) {
            float keep = kb1 ? r32[(h * 2 + 1) * 8 + lo] : r32[(h * 2) * 8 + lo];
            float send = kb1 ? r32[(h * 2) * 8 + lo]     : r32[(h * 2 + 1) * 8 + lo];
            r16[h * 8 + lo] = keep + __shfl_xor_sync(0xffffffffu, send, 2);
        }
    }
    float r8[8];
#pragma unroll
    for (int lo = 0; lo < 8; lo++) {
        float keep = kb2 ? r16[8 + lo] : r16[lo];
        float send = kb2 ? r16[lo]     : r16[8 + lo];
        r8[lo] = keep + __shfl_xor_sync(0xffffffffu, send, 4);
    }

    int vox = blockIdx.x * 16 + (tid >> 3);
    int m = vox / AA, a = vox % AA;
    float* vbase = g_v0 + (size_t)m * 64 * AA + a;
#pragma unroll
    for (int lo = 0; lo < 8; lo++)
        vbase[(k * 8 + lo) * AA] = tf32r(r8[lo]);
}

// ---------------- conv1 via implicit GEMM, mma.sync tf32, 2 samples/block ----------------
// R12/R14 version (explicit B prefetch is load-bearing; staging loop untouched).
#define C1_Q 3600
__global__ __launch_bounds__(256) void conv1_kernel(const float* __restrict__ bias) {
    __shared__ float sin[2 * C1_Q];
    __shared__ int   ktbl[27];
    __shared__ float sbias[96];

    int tid = threadIdx.x;
    int warp = tid >> 5;
    int lane = tid & 31;
    int g   = lane >> 2;
    int tig = lane & 3;
    int warpM = warp & 3;
    int warpN = warp >> 2;
    int nb = warpN * 48;

    if (tid < 27) {
        int kz = tid / 9, r = tid % 9, ky = r / 3, kx = r % 3;
        ktbl[tid] = kz * 25 + ky * 5 + kx;
    }
    if (tid < 96) sbias[tid] = bias[tid];

    int s_lo = warpM * 16 + g;
    int s_hi = s_lo + 8;
    int s_hic = (s_hi > 62) ? 62 : s_hi;
    int zlo = s_lo / 9, rlo = s_lo % 9;
    int solo = zlo * 25 + (rlo / 3) * 5 + (rlo % 3);
    int zhi = s_hic / 9, rhi = s_hic % 9;
    int sohi = zhi * 25 + (rhi / 3) * 5 + (rhi % 3);

    float acc[2][6][4];
#pragma unroll
    for (int sm = 0; sm < 2; sm++)
#pragma unroll
        for (int f = 0; f < 6; f++)
#pragma unroll
            for (int j = 0; j < 4; j++) acc[sm][f][j] = 0.f;

    const float* pWB = g_wb + warpN * 384 + lane * 12;
    float4 q0 = *(const float4*)(pWB);
    float4 q1 = *(const float4*)(pWB + 4);
    float4 q2 = *(const float4*)(pWB + 8);
    pWB += 768;

    const float* src0 = g_v0 + (size_t)(2 * blockIdx.x) * 14400;
    const float* src1 = src0 + 14400;

    for (int quarter = 0; quarter < 4; quarter++) {
        __syncthreads();
        {
            const float4* s40 = (const float4*)(src0 + quarter * C1_Q);
            const float4* s41 = (const float4*)(src1 + quarter * C1_Q);
            float4* d4 = (float4*)sin;
            for (int i = tid; i < 900; i += 256) {
                d4[i]       = s40[i];
                d4[900 + i] = s41[i];
            }
        }
        __syncthreads();

        int rr0 = tig, rr1 = tig + 4;
        int icoff0 = 0, icoff1 = 0;
        for (int ts = 0; ts < 54; ts++) {
            float4 n0 = *(const float4*)(pWB);
            float4 n1 = *(const float4*)(pWB + 4);
            float4 n2 = *(const float4*)(pWB + 8);
            pWB += 768;
            int kt0 = ktbl[rr0];
            int kt1 = ktbl[rr1];
            int i00 = icoff0 + kt0 + solo;
            int i01 = icoff0 + kt0 + sohi;
            int i10 = icoff1 + kt1 + solo;
            int i11 = icoff1 + kt1 + sohi;
            unsigned a0 = __float_as_uint(sin[i00]);
            unsigned a1 = __float_as_uint(sin[i01]);
            unsigned a2 = __float_as_uint(sin[i10]);
            unsigned a3 = __float_as_uint(sin[i11]);
            unsigned b0 = __float_as_uint(sin[C1_Q + i00]);
            unsigned b1 = __float_as_uint(sin[C1_Q + i01]);
            unsigned b2 = __float_as_uint(sin[C1_Q + i10]);
            unsigned b3 = __float_as_uint(sin[C1_Q + i11]);
            rr0 += 8; if (rr0 >= 27) { rr0 -= 27; icoff0 += 225; }
            rr1 += 8; if (rr1 >= 27) { rr1 -= 27; icoff1 += 225; }
            mma_tf32(acc[0][0][0], acc[0][0][1], acc[0][0][2], acc[0][0][3], a0, a1, a2, a3,
                     __float_as_uint(q0.x), __float_as_uint(q0.y));
            mma_tf32(acc[1][0][0], acc[1][0][1], acc[1][0][2], acc[1][0][3], b0, b1, b2, b3,
                     __float_as_uint(q0.x), __float_as_uint(q0.y));
            mma_tf32(acc[0][1][0], acc[0][1][1], acc[0][1][2], acc[0][1][3], a0, a1, a2, a3,
                     __float_as_uint(q0.z), __float_as_uint(q0.w));
            mma_tf32(acc[1][1][0], acc[1][1][1], acc[1][1][2], acc[1][1][3], b0, b1, b2, b3,
                     __float_as_uint(q0.z), __float_as_uint(q0.w));
            mma_tf32(acc[0][2][0], acc[0][2][1], acc[0][2][2], acc[0][2][3], a0, a1, a2, a3,
                     __float_as_uint(q1.x), __float_as_uint(q1.y));
            mma_tf32(acc[1][2][0], acc[1][2][1], acc[1][2][2], acc[1][2][3], b0, b1, b2, b3,
                     __float_as_uint(q1.x), __float_as_uint(q1.y));
            mma_tf32(acc[0][3][0], acc[0][3][1], acc[0][3][2], acc[0][3][3], a0, a1, a2, a3,
                     __float_as_uint(q1.z), __float_as_uint(q1.w));
            mma_tf32(acc[1][3][0], acc[1][3][1], acc[1][3][2], acc[1][3][3], b0, b1, b2, b3,
                     __float_as_uint(q1.z), __float_as_uint(q1.w));
            mma_tf32(acc[0][4][0], acc[0][4][1], acc[0][4][2], acc[0][4][3], a0, a1, a2, a3,
                     __float_as_uint(q2.x), __float_as_uint(q2.y));
            mma_tf32(acc[1][4][0], acc[1][4][1], acc[1][4][2], acc[1][4][3], b0, b1, b2, b3,
                     __float_as_uint(q2.x), __float_as_uint(q2.y));
            mma_tf32(acc[0][5][0], acc[0][5][1], acc[0][5][2], acc[0][5][3], a0, a1, a2, a3,
                     __float_as_uint(q2.z), __float_as_uint(q2.w));
            mma_tf32(acc[1][5][0], acc[1][5][1], acc[1][5][2], acc[1][5][3], b0, b1, b2, b3,
                     __float_as_uint(q2.z), __float_as_uint(q2.w));
            q0 = n0; q1 = n1; q2 = n2;
        }
    }

#pragma unroll
    for (int sm = 0; sm < 2; sm++) {
        float* outb = g_c1 + (size_t)(2 * blockIdx.x + sm) * 96 * 63;
#pragma unroll
        for (int f = 0; f < 6; f++) {
            int oc0 = nb + f * 8 + 2 * tig;
            int oc1 = oc0 + 1;
            float b0 = sbias[oc0], b1 = sbias[oc1];
            outb[oc0 * 63 + s_lo] = tf32r(fmaxf(acc[sm][f][0] + b0, 0.f));
            outb[oc1 * 63 + s_lo] = tf32r(fmaxf(acc[sm][f][1] + b1, 0.f));
            if (s_hi < 63) {
                outb[oc0 * 63 + s_hi] = tf32r(fmaxf(acc[sm][f][2] + b0, 0.f));
                outb[oc1 * 63 + s_hi] = tf32r(fmaxf(acc[sm][f][3] + b1, 0.f));
            }
        }
    }
}

// ---------------- conv2 via implicit GEMM, mma.sync tf32 (R14 version) ----------------
__global__ __launch_bounds__(256) void conv2_kernel(const float* __restrict__ bias) {
    __shared__ float sin[12096];   // 2 x 96 x 63
    __shared__ int   ktbl[27];
    __shared__ float sbias[128];

    int tid = threadIdx.x;
    int warp = tid >> 5;
    int lane = tid & 31;
    int g   = lane >> 2;
    int tig = lane & 3;

    if (tid < 27) {
        int kz = tid / 9, r = tid % 9, ky = r / 3, kx = r % 3;
        ktbl[tid] = kz * 9 + ky * 3 + kx;
    }
    if (tid < 128) sbias[tid] = bias[tid];

    {
        const float4* s4 = (const float4*)(g_c1 + (size_t)blockIdx.x * 12096);
        float4* d4 = (float4*)sin;
        for (int i = tid; i < 3024; i += 256) d4[i] = s4[i];
    }
    __syncthreads();

    int sub0 = (g < 5) ? 0 : 1;
    int z0   = (g < 5) ? g : g - 5;
    int base0 = sub0 * 6048 + z0 * 9;
    bool p1 = (g < 2);
    int base1 = 6048 + (g + 3) * 9;

    float acc[2][4];
#pragma unroll
    for (int nf = 0; nf < 2; nf++)
#pragma unroll
        for (int j = 0; j < 4; j++) acc[nf][j] = 0.f;

    const float* pWB = g_w2b + warp * 128 + lane * 4;
    float4 q = *(const float4*)pWB;
    pWB += 1024;

    int rr0 = tig, rr1 = tig + 4;
    int icoff0 = 0, icoff1 = 0;
    for (int ts = 0; ts < 324; ts++) {
        float4 n = *(const float4*)pWB;
        pWB += 1024;
        int o0 = ktbl[rr0];
        int o1 = ktbl[rr1];
        unsigned a0 = __float_as_uint(sin[base0 + icoff0 + o0]);
        unsigned a1 = p1 ? __float_as_uint(sin[base1 + icoff0 + o0]) : 0u;
        unsigned a2 = __float_as_uint(sin[base0 + icoff1 + o1]);
        unsigned a3 = p1 ? __float_as_uint(sin[base1 + icoff1 + o1]) : 0u;
        rr0 += 8; if (rr0 >= 27) { rr0 -= 27; icoff0 += 63; }
        rr1 += 8; if (rr1 >= 27) { rr1 -= 27; icoff1 += 63; }
        mma_tf32(acc[0][0], acc[0][1], acc[0][2], acc[0][3], a0, a1, a2, a3,
                 __float_as_uint(q.x), __float_as_uint(q.y));
        mma_tf32(acc[1][0], acc[1][1], acc[1][2], acc[1][3], a0, a1, a2, a3,
                 __float_as_uint(q.z), __float_as_uint(q.w));
        q = n;
    }

    int m0 = blockIdx.x * 2 + sub0;
    int m1 = blockIdx.x * 2 + 1;
#pragma unroll
    for (int nf = 0; nf < 2; nf++) {
        int oc0 = warp * 16 + nf * 8 + 2 * tig;
        int oc1 = oc0 + 1;
        float b0 = sbias[oc0], b1 = sbias[oc1];
        g_c2[(m0 * 128 + oc0) * 5 + z0] = fmaxf(acc[nf][0] + b0, 0.f);
        g_c2[(m0 * 128 + oc1) * 5 + z0] = fmaxf(acc[nf][1] + b1, 0.f);
        if (p1) {
            g_c2[(m1 * 128 + oc0) * 5 + (g + 3)] = fmaxf(acc[nf][2] + b0, 0.f);
            g_c2[(m1 * 128 + oc1) * 5 + (g + 3)] = fmaxf(acc[nf][3] + b1, 0.f);
        }
    }
}

// ---------------- fused conv3 + gates_x (4 samples/block: wt3 reuse) ----------------
__global__ __launch_bounds__(256) void vec_kernel(const float* __restrict__ b3,
                                                  const float* __restrict__ wi,
                                                  const float* __restrict__ lb) {
    int tid = threadIdx.x;
    __shared__ float sin[4 * 640];
    __shared__ float sp[256];
    __shared__ float sv[64];
    const float* src = g_c2 + (size_t)blockIdx.x * 4 * 640;
    for (int i = tid; i < 2560; i += 256) sin[i] = src[i];
    __syncthreads();
    int q = tid >> 6;
    int j = tid & 63;
    int base = q * 160;
    for (int s = 0; s < 4; s++) {
        float acc = 0.f;
        const float* sb = sin + s * 640 + base;
#pragma unroll 8
        for (int i = 0; i < 160; i++)
            acc = fmaf(sb[i], g_wt3[(base + i) * 64 + j], acc);
        sp[tid] = acc;
        __syncthreads();
        if (tid < 64)
            sv[tid] = ((sp[tid] + sp[64 + tid]) + (sp[128 + tid] + sp[192 + tid])) + b3[tid];
        __syncthreads();
        float a2 = lb[tid];
#pragma unroll
        for (int i = 0; i < 64; i++) a2 = fmaf(sv[i], wi[i * 256 + tid], a2);
        g_gx[((size_t)blockIdx.x * 4 + s) * 256 + tid] = a2;
    }
}

// ---------------- LSTM scan ----------------
__device__ __forceinline__ float sigmoidf_(float x) { return 1.0f / (1.0f + expf(-x)); }

__global__ __launch_bounds__(256) void lstm_kernel(const float* __restrict__ h0,
                                                   const float* __restrict__ c0,
                                                   const float* __restrict__ wh,
                                                   float* __restrict__ out_avec,
                                                   float* __restrict__ out_hn,
                                                   float* __restrict__ out_cn) {
    int b = blockIdx.x; int j = threadIdx.x;
    __shared__ float sh[64], sc[64], sg[256];
    float whreg[64];
#pragma unroll
    for (int i = 0; i < 64; i++) whreg[i] = wh[i * 256 + j];
    if (j < 64) { sh[j] = h0[b * 64 + j]; sc[j] = c0[b * 64 + j]; }
    __syncthreads();
    for (int t = 0; t < 64; t++) {
        float acc = g_gx[(b * 64 + t) * 256 + j];
#pragma unroll
        for (int i = 0; i < 64; i++) acc = fmaf(sh[i], whreg[i], acc);
        sg[j] = acc;
        __syncthreads();
        if (j < 64) {
            float ig = sigmoidf_(sg[j]);
            float fg = sigmoidf_(sg[64 + j]);
            float gg = tanhf(sg[128 + j]);
            float og = sigmoidf_(sg[192 + j]);
            float c = fg * sc[j] + ig * gg;
            float h = og * tanhf(c);
            sc[j] = c; sh[j] = h;
            out_avec[(b * 64 + t) * 64 + j] = h;
        }
        __syncthreads();
    }
    if (j < 64) { out_hn[b * 64 + j] = sh[j]; out_cn[b * 64 + j] = sc[j]; }
}

// ---------------- launch ----------------
extern "C" void kernel_launch(void* const* d_in, const int* in_sizes, int n_in,
                              void* d_out, int out_size) {
    (void)in_sizes; (void)n_in; (void)out_size;
    const float* x       = (const float*)d_in[0];
    const float* g_loc   = (const float*)d_in[1];
    const float* h0      = (const float*)d_in[2];
    const float* c0      = (const float*)d_in[3];
    const float* pn_w1   = (const float*)d_in[4];
    const float* pn_b1   = (const float*)d_in[5];
    const float* pn_w2   = (const float*)d_in[6];
    const float* pn_b2   = (const float*)d_in[7];
    const float* pn_w3   = (const float*)d_in[8];
    const float* pn_b3   = (const float*)d_in[9];
    const float* attn_w  = (const float*)d_in[10];
    const float* attn_b  = (const float*)d_in[11];
    const float* vx_w1   = (const float*)d_in[12];
    const float* vx_b1   = (const float*)d_in[13];
    const float* vx_w2   = (const float*)d_in[14];
    const float* vx_b2   = (const float*)d_in[15];
    const float* vx_w3   = (const float*)d_in[16];
    const float* vx_b3   = (const float*)d_in[17];
    const float* lstm_wi = (const float*)d_in[18];
    const float* lstm_wh = (const float*)d_in[19];
    const float* lstm_b  = (const float*)d_in[20];

    float* out      = (float*)d_out;
    float* out_avec = out;
    float* out_attn = out + 65536;
    float* out_hn   = out + 65536 + 1843200;
    float* out_cn   = out_hn + 1024;

    prep_kernel<<<1024 + 1302, 256>>>(x, g_loc, vx_w1, vx_w2, vx_w3, pn_w2, pn_w3);
    pointnet_attn_kernel<<<14400, 128>>>(pn_w1, pn_b1, pn_b2,
                                         pn_b3, attn_w, attn_b, out_attn);
    conv1_kernel<<<512, 256>>>(vx_b1);
    conv2_kernel<<<512, 256>>>(vx_b2);
    vec_kernel<<<256, 256>>>(vx_b3, lstm_wi, lstm_b);
    lstm_kernel<<<16, 256>>>(h0, c0, lstm_wh, out_avec, out_hn, out_cn);
}

// round 17
// speedup vs baseline: 1.1464x; 1.0557x over previous
#include <cuda_runtime.h>
#include <math.h>

#define MM 1024
#define NPT 128
#define AA 225
#define NSK 8

typedef unsigned long long ull;

__device__ __forceinline__ ull fma2(ull a, ull b, ull c) {
    ull d;
    asm("fma.rn.f32x2 %0, %1, %2, %3;" : "=l"(d) : "l"(a), "l"(b), "l"(c));
    return d;
}
__device__ __forceinline__ ull pack2(float x, float y) {
    ull d;
    asm("mov.b64 %0, {%1, %2};" : "=l"(d) : "f"(x), "f"(y));
    return d;
}
__device__ __forceinline__ float2 unpack2(ull v) {
    float2 r;
    asm("mov.b64 {%0, %1}, %2;" : "=f"(r.x), "=f"(r.y) : "l"(v));
    return r;
}
__device__ __forceinline__ float tf32r(float x) {
    float y;
    asm("cvt.rna.tf32.f32 %0, %1;" : "=f"(y) : "f"(x));
    return y;
}
__device__ __forceinline__ void mma_tf32(float& c0, float& c1, float& c2, float& c3,
                                         unsigned a0, unsigned a1, unsigned a2, unsigned a3,
                                         unsigned b0, unsigned b1) {
    asm volatile("mma.sync.aligned.m16n8k8.row.col.f32.tf32.tf32.f32 "
                 "{%0,%1,%2,%3}, {%4,%5,%6,%7}, {%8,%9}, {%0,%1,%2,%3};"
                 : "+f"(c0), "+f"(c1), "+f"(c2), "+f"(c3)
                 : "r"(a0), "r"(a1), "r"(a2), "r"(a3), "r"(b0), "r"(b1));
}

// ---------------- scratch ----------------
__device__ __align__(16) float g_grouped[MM * AA * NSK * 5];
__device__ __align__(16) float g_v0[MM * 64 * AA];
__device__ __align__(16) float g_c1[MM * 96 * 63];
__device__ __align__(16) float g_c2[MM * 128 * 5];
__device__ __align__(16) float g_gx[MM * 256];
__device__ __align__(16) float g_wb[217 * 768];     // conv1 W fragment order (+1 ts pad)
__device__ __align__(16) float g_w3b[2048];         // pointnet W3 fragment order
__device__ __align__(16) float g_w2pb[512];         // pointnet W2 fragment order
__device__ __align__(16) float g_w2b[333056];       // conv2 W fragment order (+pad)
__device__ __align__(16) float g_wt3[640 * 64];     // [k][oc]

// ---------------- fused prep: blocks <1024 do KNN; rest pack weights ----------------
__global__ __launch_bounds__(256) void prep_kernel(
    const float* __restrict__ x, const float* __restrict__ g_loc,
    const float* __restrict__ w1, const float* __restrict__ w2,
    const float* __restrict__ w3, const float* __restrict__ pw2,
    const float* __restrict__ pw3) {
    int tid = threadIdx.x;
    if (blockIdx.x >= 1024) {
        int i = (blockIdx.x - 1024) * 256 + tid;
        if (i < 216 * 768) {
            int ts = i / 768;
            int r  = i % 768;
            int wn = r / 384;
            int r2 = r % 384;
            int lane = r2 / 12;
            int j = r2 % 12;
            int f = j >> 1, half = j & 1;
            int g = lane >> 2, tig = lane & 3;
            int k  = ts * 8 + tig + half * 4;
            int oc = wn * 48 + f * 8 + g;
            g_wb[i] = tf32r(w1[oc * 1728 + k]);
        } else if (i < 217 * 768) {
            g_wb[i] = 0.f;
        }
        if (i < 2048) {
            int kt = i >> 9;
            int r  = i & 511;
            int lane = r >> 4;
            int j = r & 15;
            int nf = j >> 1, half = j & 1;
            int g = lane >> 2, tig = lane & 3;
            int row = kt * 8 + tig + half * 4;
            int col = nf * 8 + g;
            g_w3b[i] = tf32r(pw3[row * 64 + col]);
        }
        if (i < 512) {
            int kt = i >> 8;
            int r  = i & 255;
            int lane = r >> 3;
            int j = r & 7;
            int nf = j >> 1, half = j & 1;
            int g = lane >> 2, tig = lane & 3;
            int k   = kt * 8 + tig + half * 4;
            int col = nf * 8 + g;
            g_w2pb[i] = tf32r(pw2[k * 32 + col]);
        }
        if (i < 331776) {
            int ts_wn = i >> 7;
            int r     = i & 127;
            int lane  = r >> 2;
            int j     = r & 3;
            int nf = j >> 1, half = j & 1;
            int g = lane >> 2, tig = lane & 3;
            int wn = ts_wn & 7;
            int ts = ts_wn >> 3;
            int k  = ts * 8 + tig + half * 4;
            int oc = wn * 16 + nf * 8 + g;
            g_w2b[i] = tf32r(w2[oc * 2592 + k]);
        } else if (i < 333056) {
            g_w2b[i] = 0.f;
        }
        if (i < 64 * 640) g_wt3[(i % 640) * 64 + (i / 640)] = w3[i];
        return;
    }
    // ---- KNN branch ----
    int m = blockIdx.x;
    __shared__ float px[NPT], py[NPT], pz[NPT], p0[NPT], p1[NPT], pn2[NPT];
    if (tid < NPT) {
        const float* xp = x + (m * NPT + tid) * 5;
        float a = xp[0], b = xp[1], c = xp[2];
        px[tid] = a; py[tid] = b; pz[tid] = c;
        p0[tid] = xp[3]; p1[tid] = xp[4];
        pn2[tid] = a * a + b * b + c * c;
    }
    __syncthreads();
    if (tid >= AA) return;
    int aI = tid;
    int zi = aI / 25, rem = aI % 25, yi = rem / 5, xi = rem % 5;
    float ax = ((float)xi - 2.0f) * 0.2f + g_loc[m * 2 + 0];
    float ay = ((float)yi - 2.0f) * 0.2f + g_loc[m * 2 + 1];
    float az = (float)zi * 0.22f + 0.1f;
    float an2 = ax * ax + ay * ay + az * az;

    float bd[NSK]; int bix[NSK];
#pragma unroll
    for (int k = 0; k < NSK; k++) { bd[k] = 3.4e38f; bix[k] = 0; }
    for (int n = 0; n < NPT; n++) {
        float d = an2 - 2.0f * (ax * px[n] + ay * py[n] + az * pz[n]) + pn2[n];
        if (d < bd[NSK - 1]) {
            float cd = d; int ci = n;
#pragma unroll
            for (int k = 0; k < NSK; k++) {
                if (cd < bd[k]) {
                    float td = bd[k]; int ti = bix[k];
                    bd[k] = cd; bix[k] = ci; cd = td; ci = ti;
                }
            }
        }
    }
    float* gp = g_grouped + (m * AA + aI) * NSK * 5;
#pragma unroll
    for (int k = 0; k < NSK; k++) {
        int n = bix[k];
        gp[k * 5 + 0] = px[n] - ax;
        gp[k * 5 + 1] = py[n] - ay;
        gp[k * 5 + 2] = pz[n] - az;
        gp[k * 5 + 3] = p0[n];
        gp[k * 5 + 4] = p1[n];
    }
}

// ---------------- PointNet: layer1 scalar, layers 2+3 tensor-core ----------
__global__ __launch_bounds__(128) void pointnet_attn_kernel(
    const float* __restrict__ w1, const float* __restrict__ b1,
    const float* __restrict__ b2, const float* __restrict__ b3,
    const float* __restrict__ aw, const float* __restrict__ ab,
    float* __restrict__ out_attn) {
    __shared__ __align__(16) float sX[128 * 66];
    __shared__ __align__(16) float sw[256];
    float* sw1 = sw;
    float* sb1 = sw + 80;
    float* sb2 = sw + 96;
    float* sb3 = sw + 128;
    float* saw = sw + 192;
    int tid = threadIdx.x;
    for (int i = tid; i < 80; i += 128) sw1[i] = w1[i];
    if (tid < 16) sb1[tid] = b1[tid];
    if (tid < 32) sb2[tid] = b2[tid];
    if (tid < 64) sb3[tid] = b3[tid];
    if (tid < 64) saw[tid] = aw[tid];
    __syncthreads();
    float abv = ab[0];

    const float* gin = g_grouped + ((size_t)blockIdx.x * 128 + tid) * 5;
    float xin[5];
    xin[0] = gin[0]; xin[1] = gin[1]; xin[2] = gin[2]; xin[3] = gin[3]; xin[4] = gin[4];

    float h1[16];
    {
        ull a1[8];
#pragma unroll
        for (int p = 0; p < 8; p++) a1[p] = ((const ull*)sb1)[p];
#pragma unroll
        for (int i = 0; i < 5; i++) {
            ull hh = pack2(xin[i], xin[i]);
            const ulonglong2* wr = (const ulonglong2*)&sw1[i * 16];
#pragma unroll
            for (int q = 0; q < 4; q++) {
                ulonglong2 wv = wr[q];
                a1[2 * q]     = fma2(hh, wv.x, a1[2 * q]);
                a1[2 * q + 1] = fma2(hh, wv.y, a1[2 * q + 1]);
            }
        }
#pragma unroll
        for (int p = 0; p < 8; p++) {
            float2 v = unpack2(a1[p]);
            h1[2 * p] = fmaxf(v.x, 0.f); h1[2 * p + 1] = fmaxf(v.y, 0.f);
        }
    }
    {
        float* xr = sX + tid * 36;
#pragma unroll
        for (int j = 0; j < 16; j += 4) {
            float4 v;
            v.x = tf32r(h1[j]);     v.y = tf32r(h1[j + 1]);
            v.z = tf32r(h1[j + 2]); v.w = tf32r(h1[j + 3]);
            *(float4*)(xr + j) = v;
        }
    }
    __syncthreads();

    int warp = tid >> 5, lane = tid & 31, g = lane >> 2, tig = lane & 3;

    // ---- layer2 MMA: [128 x 16] @ [16 x 32] ----
    {
        unsigned b2f[2][4][2];
        {
            const float4* wb2 = (const float4*)g_w2pb;
#pragma unroll
            for (int kt = 0; kt < 2; kt++) {
                float4 v0 = wb2[kt * 64 + lane * 2];
                float4 v1 = wb2[kt * 64 + lane * 2 + 1];
                b2f[kt][0][0] = __float_as_uint(v0.x); b2f[kt][0][1] = __float_as_uint(v0.y);
                b2f[kt][1][0] = __float_as_uint(v0.z); b2f[kt][1][1] = __float_as_uint(v0.w);
                b2f[kt][2][0] = __float_as_uint(v1.x); b2f[kt][2][1] = __float_as_uint(v1.y);
                b2f[kt][3][0] = __float_as_uint(v1.z); b2f[kt][3][1] = __float_as_uint(v1.w);
            }
        }
        unsigned a2f[2][2][4];
#pragma unroll
        for (int mt = 0; mt < 2; mt++) {
            int r0 = warp * 32 + mt * 16 + g;
            const float* x0 = sX + r0 * 36;
            const float* x1 = sX + (r0 + 8) * 36;
#pragma unroll
            for (int kt = 0; kt < 2; kt++) {
                int c0 = kt * 8 + tig;
                a2f[mt][kt][0] = __float_as_uint(x0[c0]);
                a2f[mt][kt][1] = __float_as_uint(x1[c0]);
                a2f[mt][kt][2] = __float_as_uint(x0[c0 + 4]);
                a2f[mt][kt][3] = __float_as_uint(x1[c0 + 4]);
            }
        }
        float acc2[2][4][4];
#pragma unroll
        for (int mt = 0; mt < 2; mt++)
#pragma unroll
            for (int nf = 0; nf < 4; nf++)
#pragma unroll
                for (int j = 0; j < 4; j++) acc2[mt][nf][j] = 0.f;
#pragma unroll
        for (int mt = 0; mt < 2; mt++)
#pragma unroll
            for (int kt = 0; kt < 2; kt++)
#pragma unroll
                for (int nf = 0; nf < 4; nf++)
                    mma_tf32(acc2[mt][nf][0], acc2[mt][nf][1], acc2[mt][nf][2], acc2[mt][nf][3],
                             a2f[mt][kt][0], a2f[mt][kt][1], a2f[mt][kt][2], a2f[mt][kt][3],
                             b2f[kt][nf][0], b2f[kt][nf][1]);
        __syncthreads();
#pragma unroll
        for (int mt = 0; mt < 2; mt++) {
            int r0 = warp * 32 + mt * 16 + g;
#pragma unroll
            for (int nf = 0; nf < 4; nf++) {
                int c0 = nf * 8 + 2 * tig;
                float bb0 = sb2[c0], bb1 = sb2[c0 + 1];
                float2 v0 = make_float2(tf32r(fmaxf(acc2[mt][nf][0] + bb0, 0.f)),
                                        tf32r(fmaxf(acc2[mt][nf][1] + bb1, 0.f)));
                float2 v1 = make_float2(tf32r(fmaxf(acc2[mt][nf][2] + bb0, 0.f)),
                                        tf32r(fmaxf(acc2[mt][nf][3] + bb1, 0.f)));
                *(float2*)(sX + r0 * 36 + c0)       = v0;
                *(float2*)(sX + (r0 + 8) * 36 + c0) = v1;
            }
        }
    }
    __syncthreads();

    // ---- layer3 MMA: [128 x 32] @ [32 x 64] ----
    unsigned bf[4][8][2];
    {
        const float4* wb = (const float4*)g_w3b;
#pragma unroll
        for (int kt = 0; kt < 4; kt++) {
#pragma unroll
            for (int q = 0; q < 4; q++) {
                float4 v = wb[kt * 128 + lane * 4 + q];
                bf[kt][2 * q][0]     = __float_as_uint(v.x);
                bf[kt][2 * q][1]     = __float_as_uint(v.y);
                bf[kt][2 * q + 1][0] = __float_as_uint(v.z);
                bf[kt][2 * q + 1][1] = __float_as_uint(v.w);
            }
        }
    }
    float acc[2][8][4];
#pragma unroll
    for (int mt = 0; mt < 2; mt++)
#pragma unroll
        for (int nf = 0; nf < 8; nf++)
#pragma unroll
            for (int j = 0; j < 4; j++) acc[mt][nf][j] = 0.f;

#pragma unroll
    for (int mt = 0; mt < 2; mt++) {
        int r0 = (warp * 2 + mt) * 16 + g;
        const float* x0 = sX + r0 * 36;
        const float* x1 = sX + (r0 + 8) * 36;
#pragma unroll
        for (int kt = 0; kt < 4; kt++) {
            int c0 = kt * 8 + tig;
            unsigned a0 = __float_as_uint(x0[c0]);
            unsigned a1 = __float_as_uint(x1[c0]);
            unsigned a2 = __float_as_uint(x0[c0 + 4]);
            unsigned a3 = __float_as_uint(x1[c0 + 4]);
#pragma unroll
            for (int nf = 0; nf < 8; nf++)
                mma_tf32(acc[mt][nf][0], acc[mt][nf][1], acc[mt][nf][2], acc[mt][nf][3],
                         a0, a1, a2, a3, bf[kt][nf][0], bf[kt][nf][1]);
        }
    }
    __syncthreads();

#pragma unroll
    for (int mt = 0; mt < 2; mt++) {
        int r0 = (warp * 2 + mt) * 16 + g;
#pragma unroll
        for (int nf = 0; nf < 8; nf++) {
            int col = nf * 8 + 2 * tig;
            float bb0 = sb3[col], bb1 = sb3[col + 1];
            float2 v0 = make_float2(fmaxf(acc[mt][nf][0] + bb0, 0.f),
                                    fmaxf(acc[mt][nf][1] + bb1, 0.f));
            float2 v1 = make_float2(fmaxf(acc[mt][nf][2] + bb0, 0.f),
                                    fmaxf(acc[mt][nf][3] + bb1, 0.f));
            *(float2*)(sX + r0 * 66 + col)       = v0;
            *(float2*)(sX + (r0 + 8) * 66 + col) = v1;
        }
    }
    __syncthreads();

    float f[64];
    {
        const float* fr = sX + tid * 66;
#pragma unroll
        for (int c = 0; c < 64; c += 2) {
            float2 v = *(const float2*)(fr + c);
            f[c] = v.x; f[c + 1] = v.y;
        }
    }
    int k = tid & 7;
    float logit = abv;
#pragma unroll
    for (int c = 0; c < 64; c++) logit = fmaf(f[c], saw[c], logit);

    float mx = logit;
    mx = fmaxf(mx, __shfl_xor_sync(0xffffffffu, mx, 1));
    mx = fmaxf(mx, __shfl_xor_sync(0xffffffffu, mx, 2));
    mx = fmaxf(mx, __shfl_xor_sync(0xffffffffu, mx, 4));
    float e = expf(logit - mx);
    float s = e;
    s += __shfl_xor_sync(0xffffffffu, s, 1);
    s += __shfl_xor_sync(0xffffffffu, s, 2);
    s += __shfl_xor_sync(0xffffffffu, s, 4);
    float attn = e / s;
    out_attn[(size_t)blockIdx.x * 128 + tid] = attn;

#pragma unroll
    for (int c = 0; c < 64; c++) f[c] *= attn;

    bool kb0 = (k & 1) != 0, kb1 = (k & 2) != 0, kb2 = (k & 4) != 0;
    float r32[32];
#pragma unroll
    for (int h = 0; h < 4; h++) {
#pragma unroll
        for (int lo = 0; lo < 8; lo++) {
            float keep = kb0 ? f[(h * 2 + 1) * 8 + lo] : f[(h * 2) * 8 + lo];
            float send = kb0 ? f[(h * 2) * 8 + lo]     : f[(h * 2 + 1) * 8 + lo];
            r32[h * 8 + lo] = keep + __shfl_xor_sync(0xffffffffu, send, 1);
        }
    }
    float r16[16];
#pragma unroll
    for (int h = 0; h < 2; h++) {
#pragma unroll
        for (int lo = 0; lo < 8; lo++) {
            float keep = kb1 ? r32[(h * 2 + 1) * 8 + lo] : r32[(h * 2) * 8 + lo];
            float send = kb1 ? r32[(h * 2) * 8 + lo]     : r32[(h * 2 + 1) * 8 + lo];
            r16[h * 8 + lo] = keep + __shfl_xor_sync(0xffffffffu, send, 2);
        }
    }
    float r8[8];
#pragma unroll
    for (int lo = 0; lo < 8; lo++) {
        float keep = kb2 ? r16[8 + lo] : r16[lo];
        float send = kb2 ? r16[lo]     : r16[8 + lo];
        r8[lo] = keep + __shfl_xor_sync(0xffffffffu, send, 4);
    }

    int vox = blockIdx.x * 16 + (tid >> 3);
    int m = vox / AA, a = vox % AA;
    float* vbase = g_v0 + (size_t)m * 64 * AA + a;
#pragma unroll
    for (int lo = 0; lo < 8; lo++)
        vbase[(k * 8 + lo) * AA] = tf32r(r8[lo]);
}

// ---------------- conv1 via implicit GEMM, mma.sync tf32, 2 samples/block ----------------
#define C1_Q 3600
__global__ __launch_bounds__(256) void conv1_kernel(const float* __restrict__ bias) {
    __shared__ float sin[2 * C1_Q];
    __shared__ int   ktbl[27];
    __shared__ float sbias[96];

    int tid = threadIdx.x;
    int warp = tid >> 5;
    int lane = tid & 31;
    int g   = lane >> 2;
    int tig = lane & 3;
    int warpM = warp & 3;
    int warpN = warp >> 2;
    int nb = warpN * 48;

    if (tid < 27) {
        int kz = tid / 9, r = tid % 9, ky = r / 3, kx = r % 3;
        ktbl[tid] = kz * 25 + ky * 5 + kx;
    }
    if (tid < 96) sbias[tid] = bias[tid];

    int s_lo = warpM * 16 + g;
    int s_hi = s_lo + 8;
    int s_hic = (s_hi > 62) ? 62 : s_hi;
    int zlo = s_lo / 9, rlo = s_lo % 9;
    int solo = zlo * 25 + (rlo / 3) * 5 + (rlo % 3);
    int zhi = s_hic / 9, rhi = s_hic % 9;
    int sohi = zhi * 25 + (rhi / 3) * 5 + (rhi % 3);

    float acc[2][6][4];
#pragma unroll
    for (int sm = 0; sm < 2; sm++)
#pragma unroll
        for (int f = 0; f < 6; f++)
#pragma unroll
            for (int j = 0; j < 4; j++) acc[sm][f][j] = 0.f;

    const float* pWB = g_wb + warpN * 384 + lane * 12;
    float4 q0 = *(const float4*)(pWB);
    float4 q1 = *(const float4*)(pWB + 4);
    float4 q2 = *(const float4*)(pWB + 8);
    pWB += 768;

    const float* src0 = g_v0 + (size_t)(2 * blockIdx.x) * 14400;
    const float* src1 = src0 + 14400;

    for (int quarter = 0; quarter < 4; quarter++) {
        __syncthreads();
        {
            const float4* s40 = (const float4*)(src0 + quarter * C1_Q);
            const float4* s41 = (const float4*)(src1 + quarter * C1_Q);
            float4* d4 = (float4*)sin;
            for (int i = tid; i < 900; i += 256) {
                d4[i]       = s40[i];
                d4[900 + i] = s41[i];
            }
        }
        __syncthreads();

        int rr0 = tig, rr1 = tig + 4;
        int icoff0 = 0, icoff1 = 0;
        for (int ts = 0; ts < 54; ts++) {
            float4 n0 = *(const float4*)(pWB);
            float4 n1 = *(const float4*)(pWB + 4);
            float4 n2 = *(const float4*)(pWB + 8);
            pWB += 768;
            int kt0 = ktbl[rr0];
            int kt1 = ktbl[rr1];
            int i00 = icoff0 + kt0 + solo;
            int i01 = icoff0 + kt0 + sohi;
            int i10 = icoff1 + kt1 + solo;
            int i11 = icoff1 + kt1 + sohi;
            unsigned a0 = __float_as_uint(sin[i00]);
            unsigned a1 = __float_as_uint(sin[i01]);
            unsigned a2 = __float_as_uint(sin[i10]);
            unsigned a3 = __float_as_uint(sin[i11]);
            unsigned b0 = __float_as_uint(sin[C1_Q + i00]);
            unsigned b1 = __float_as_uint(sin[C1_Q + i01]);
            unsigned b2 = __float_as_uint(sin[C1_Q + i10]);
            unsigned b3 = __float_as_uint(sin[C1_Q + i11]);
            rr0 += 8; if (rr0 >= 27) { rr0 -= 27; icoff0 += 225; }
            rr1 += 8; if (rr1 >= 27) { rr1 -= 27; icoff1 += 225; }
            mma_tf32(acc[0][0][0], acc[0][0][1], acc[0][0][2], acc[0][0][3], a0, a1, a2, a3,
                     __float_as_uint(q0.x), __float_as_uint(q0.y));
            mma_tf32(acc[1][0][0], acc[1][0][1], acc[1][0][2], acc[1][0][3], b0, b1, b2, b3,
                     __float_as_uint(q0.x), __float_as_uint(q0.y));
            mma_tf32(acc[0][1][0], acc[0][1][1], acc[0][1][2], acc[0][1][3], a0, a1, a2, a3,
                     __float_as_uint(q0.z), __float_as_uint(q0.w));
            mma_tf32(acc[1][1][0], acc[1][1][1], acc[1][1][2], acc[1][1][3], b0, b1, b2, b3,
                     __float_as_uint(q0.z), __float_as_uint(q0.w));
            mma_tf32(acc[0][2][0], acc[0][2][1], acc[0][2][2], acc[0][2][3], a0, a1, a2, a3,
                     __float_as_uint(q1.x), __float_as_uint(q1.y));
            mma_tf32(acc[1][2][0], acc[1][2][1], acc[1][2][2], acc[1][2][3], b0, b1, b2, b3,
                     __float_as_uint(q1.x), __float_as_uint(q1.y));
            mma_tf32(acc[0][3][0], acc[0][3][1], acc[0][3][2], acc[0][3][3], a0, a1, a2, a3,
                     __float_as_uint(q1.z), __float_as_uint(q1.w));
            mma_tf32(acc[1][3][0], acc[1][3][1], acc[1][3][2], acc[1][3][3], b0, b1, b2, b3,
                     __float_as_uint(q1.z), __float_as_uint(q1.w));
            mma_tf32(acc[0][4][0], acc[0][4][1], acc[0][4][2], acc[0][4][3], a0, a1, a2, a3,
                     __float_as_uint(q2.x), __float_as_uint(q2.y));
            mma_tf32(acc[1][4][0], acc[1][4][1], acc[1][4][2], acc[1][4][3], b0, b1, b2, b3,
                     __float_as_uint(q2.x), __float_as_uint(q2.y));
            mma_tf32(acc[0][5][0], acc[0][5][1], acc[0][5][2], acc[0][5][3], a0, a1, a2, a3,
                     __float_as_uint(q2.z), __float_as_uint(q2.w));
            mma_tf32(acc[1][5][0], acc[1][5][1], acc[1][5][2], acc[1][5][3], b0, b1, b2, b3,
                     __float_as_uint(q2.z), __float_as_uint(q2.w));
            q0 = n0; q1 = n1; q2 = n2;
        }
    }

#pragma unroll
    for (int sm = 0; sm < 2; sm++) {
        float* outb = g_c1 + (size_t)(2 * blockIdx.x + sm) * 96 * 63;
#pragma unroll
        for (int f = 0; f < 6; f++) {
            int oc0 = nb + f * 8 + 2 * tig;
            int oc1 = oc0 + 1;
            float b0 = sbias[oc0], b1 = sbias[oc1];
            outb[oc0 * 63 + s_lo] = tf32r(fmaxf(acc[sm][f][0] + b0, 0.f));
            outb[oc1 * 63 + s_lo] = tf32r(fmaxf(acc[sm][f][1] + b1, 0.f));
            if (s_hi < 63) {
                outb[oc0 * 63 + s_hi] = tf32r(fmaxf(acc[sm][f][2] + b0, 0.f));
                outb[oc1 * 63 + s_hi] = tf32r(fmaxf(acc[sm][f][3] + b1, 0.f));
            }
        }
    }
}

// ---------------- conv2 via implicit GEMM, mma.sync tf32 ----------------
__global__ __launch_bounds__(256) void conv2_kernel(const float* __restrict__ bias) {
    __shared__ float sin[12096];   // 2 x 96 x 63
    __shared__ int   ktbl[27];
    __shared__ float sbias[128];

    int tid = threadIdx.x;
    int warp = tid >> 5;
    int lane = tid & 31;
    int g   = lane >> 2;
    int tig = lane & 3;

    if (tid < 27) {
        int kz = tid / 9, r = tid % 9, ky = r / 3, kx = r % 3;
        ktbl[tid] = kz * 9 + ky * 3 + kx;
    }
    if (tid < 128) sbias[tid] = bias[tid];

    {
        const float4* s4 = (const float4*)(g_c1 + (size_t)blockIdx.x * 12096);
        float4* d4 = (float4*)sin;
        for (int i = tid; i < 3024; i += 256) d4[i] = s4[i];
    }
    __syncthreads();

    int sub0 = (g < 5) ? 0 : 1;
    int z0   = (g < 5) ? g : g - 5;
    int base0 = sub0 * 6048 + z0 * 9;
    bool p1 = (g < 2);
    int base1 = 6048 + (g + 3) * 9;

    float acc[2][4];
#pragma unroll
    for (int nf = 0; nf < 2; nf++)
#pragma unroll
        for (int j = 0; j < 4; j++) acc[nf][j] = 0.f;

    const float* pWB = g_w2b + warp * 128 + lane * 4;
    float4 q = *(const float4*)pWB;
    pWB += 1024;

    int rr0 = tig, rr1 = tig + 4;
    int icoff0 = 0, icoff1 = 0;
    for (int ts = 0; ts < 324; ts++) {
        float4 n = *(const float4*)pWB;
        pWB += 1024;
        int o0 = ktbl[rr0];
        int o1 = ktbl[rr1];
        unsigned a0 = __float_as_uint(sin[base0 + icoff0 + o0]);
        unsigned a1 = p1 ? __float_as_uint(sin[base1 + icoff0 + o0]) : 0u;
        unsigned a2 = __float_as_uint(sin[base0 + icoff1 + o1]);
        unsigned a3 = p1 ? __float_as_uint(sin[base1 + icoff1 + o1]) : 0u;
        rr0 += 8; if (rr0 >= 27) { rr0 -= 27; icoff0 += 63; }
        rr1 += 8; if (rr1 >= 27) { rr1 -= 27; icoff1 += 63; }
        mma_tf32(acc[0][0], acc[0][1], acc[0][2], acc[0][3], a0, a1, a2, a3,
                 __float_as_uint(q.x), __float_as_uint(q.y));
        mma_tf32(acc[1][0], acc[1][1], acc[1][2], acc[1][3], a0, a1, a2, a3,
                 __float_as_uint(q.z), __float_as_uint(q.w));
        q = n;
    }

    int m0 = blockIdx.x * 2 + sub0;
    int m1 = blockIdx.x * 2 + 1;
#pragma unroll
    for (int nf = 0; nf < 2; nf++) {
        int oc0 = warp * 16 + nf * 8 + 2 * tig;
        int oc1 = oc0 + 1;
        float b0 = sbias[oc0], b1 = sbias[oc1];
        g_c2[(m0 * 128 + oc0) * 5 + z0] = fmaxf(acc[nf][0] + b0, 0.f);
        g_c2[(m0 * 128 + oc1) * 5 + z0] = fmaxf(acc[nf][1] + b1, 0.f);
        if (p1) {
            g_c2[(m1 * 128 + oc0) * 5 + (g + 3)] = fmaxf(acc[nf][2] + b0, 0.f);
            g_c2[(m1 * 128 + oc1) * 5 + (g + 3)] = fmaxf(acc[nf][3] + b1, 0.f);
        }
    }
}

// ---------------- fused conv3 + gates_x (R14 version) ----------------
__global__ __launch_bounds__(256) void vec_kernel(const float* __restrict__ b3,
                                                  const float* __restrict__ wi,
                                                  const float* __restrict__ lb) {
    int m = blockIdx.x; int tid = threadIdx.x;
    __shared__ float sin[640];
    __shared__ float sp[256];
    __shared__ float sv[64];
    const float* src = g_c2 + m * 640;
    for (int i = tid; i < 640; i += 256) sin[i] = src[i];
    __syncthreads();
    {
        int q = tid >> 6;
        int j = tid & 63;
        float acc = 0.f;
        int base = q * 160;
#pragma unroll 8
        for (int i = 0; i < 160; i++)
            acc = fmaf(sin[base + i], g_wt3[(base + i) * 64 + j], acc);
        sp[tid] = acc;
    }
    __syncthreads();
    if (tid < 64)
        sv[tid] = ((sp[tid] + sp[64 + tid]) + (sp[128 + tid] + sp[192 + tid])) + b3[tid];
    __syncthreads();
    float acc = lb[tid];
#pragma unroll
    for (int i = 0; i < 64; i++) acc = fmaf(sv[i], wi[i * 256 + tid], acc);
    g_gx[m * 256 + tid] = acc;
}

// ---------------- LSTM scan ----------------
__device__ __forceinline__ float sigmoidf_(float x) { return 1.0f / (1.0f + expf(-x)); }

__global__ __launch_bounds__(256) void lstm_kernel(const float* __restrict__ h0,
                                                   const float* __restrict__ c0,
                                                   const float* __restrict__ wh,
                                                   float* __restrict__ out_avec,
                                                   float* __restrict__ out_hn,
                                                   float* __restrict__ out_cn) {
    int b = blockIdx.x; int j = threadIdx.x;
    __shared__ float sh[64], sc[64], sg[256];
    float whreg[64];
#pragma unroll
    for (int i = 0; i < 64; i++) whreg[i] = wh[i * 256 + j];
    if (j < 64) { sh[j] = h0[b * 64 + j]; sc[j] = c0[b * 64 + j]; }
    __syncthreads();
    for (int t = 0; t < 64; t++) {
        float acc = g_gx[(b * 64 + t) * 256 + j];
#pragma unroll
        for (int i = 0; i < 64; i++) acc = fmaf(sh[i], whreg[i], acc);
        sg[j] = acc;
        __syncthreads();
        if (j < 64) {
            float ig = sigmoidf_(sg[j]);
            float fg = sigmoidf_(sg[64 + j]);
            float gg = tanhf(sg[128 + j]);
            float og = sigmoidf_(sg[192 + j]);
            float c = fg * sc[j] + ig * gg;
            float h = og * tanhf(c);
            sc[j] = c; sh[j] = h;
            out_avec[(b * 64 + t) * 64 + j] = h;
        }
        __syncthreads();
    }
    if (j < 64) { out_hn[b * 64 + j] = sh[j]; out_cn[b * 64 + j] = sc[j]; }
}

// ---------------- launch ----------------
extern "C" void kernel_launch(void* const* d_in, const int* in_sizes, int n_in,
                              void* d_out, int out_size) {
    (void)in_sizes; (void)n_in; (void)out_size;
    const float* x       = (const float*)d_in[0];
    const float* g_loc   = (const float*)d_in[1];
    const float* h0      = (const float*)d_in[2];
    const float* c0      = (const float*)d_in[3];
    const float* pn_w1   = (const float*)d_in[4];
    const float* pn_b1   = (const float*)d_in[5];
    const float* pn_w2   = (const float*)d_in[6];
    const float* pn_b2   = (const float*)d_in[7];
    const float* pn_w3   = (const float*)d_in[8];
    const float* pn_b3   = (const float*)d_in[9];
    const float* attn_w  = (const float*)d_in[10];
    const float* attn_b  = (const float*)d_in[11];
    const float* vx_w1   = (const float*)d_in[12];
    const float* vx_b1   = (const float*)d_in[13];
    const float* vx_w2   = (const float*)d_in[14];
    const float* vx_b2   = (const float*)d_in[15];
    const float* vx_w3   = (const float*)d_in[16];
    const float* vx_b3   = (const float*)d_in[17];
    const float* lstm_wi = (const float*)d_in[18];
    const float* lstm_wh = (const float*)d_in[19];
    const float* lstm_b  = (const float*)d_in[20];

    float* out      = (float*)d_out;
    float* out_avec = out;
    float* out_attn = out + 65536;
    float* out_hn   = out + 65536 + 1843200;
    float* out_cn   = out_hn + 1024;

    prep_kernel<<<1024 + 1302, 256>>>(x, g_loc, vx_w1, vx_w2, vx_w3, pn_w2, pn_w3);
    pointnet_attn_kernel<<<14400, 128>>>(pn_w1, pn_b1, pn_b2,
                                         pn_b3, attn_w, attn_b, out_attn);
    conv1_kernel<<<512, 256>>>(vx_b1);
    conv2_kernel<<<512, 256>>>(vx_b2);
    vec_kernel<<<1024, 256>>>(vx_b3, lstm_wi, lstm_b);
    lstm_kernel<<<16, 256>>>(h0, c0, lstm_wh, out_avec, out_hn, out_cn);
}